// round 9
// baseline (speedup 1.0000x reference)
#include <cuda_runtime.h>
#include <math.h>

#define NN 50000
#define EE 400000
#define DD 128
#define CC 8

#define TILE_E 32
#define NTHR 256
#define MS 132   // row stride in floats (128 used, 16B-aligned rows: 132*4=528)

// ---------------- device scratch (no allocations allowed) ----------------
__device__ float g_node_agg[NN * DD];        // 25.6 MB
__device__ float g_coord_sum[NN * CC * 3];   // 4.8 MB
__device__ float g_cnt[NN];
__device__ float g_pcol[NN * 3];
__device__ int   g_csum[NN];
__device__ unsigned int g_maxbits;
__device__ float g_Ah[NN * DD];              // h @ W1[:128]
__device__ float g_Bh[NN * DD];              // h @ W1[128:256]

// edge-pre outputs
__device__ float g_rad[EE * 8];              // radial MLP output (12.8 MB)
__device__ float g_cdiff[EE * 24];           // coord_diff (38.4 MB)
__device__ int4  g_meta[EE];                 // {tgt, src, ts, ew_bits}
__device__ float g_wr[EE];

// K-pair-interleaved packed weights: element [kp*COLS + j] = pack(w[2kp][j], w[2kp+1][j])
__device__ unsigned long long g_W1p[128 * 128];   // m_w1 rows 0..255
__device__ unsigned long long g_W2p[64 * 128];    // m_w2: 128x128
__device__ unsigned long long g_CW1p[64 * 128];   // c_w1: 128x128
__device__ unsigned long long g_HWp[64 * 128];    // het_w: 128x128
__device__ unsigned long long g_CW2p[64 * 8];     // c_w2: 128x8

__device__ __forceinline__ float silu_f(float x) {
    return x * (1.0f / (1.0f + __expf(-x)));
}

__device__ __forceinline__ unsigned long long packf2(float lo, float hi) {
    return ((unsigned long long)__float_as_uint(hi) << 32) | (unsigned long long)__float_as_uint(lo);
}
__device__ __forceinline__ float lo_f(unsigned long long p) { return __uint_as_float((unsigned)(p & 0xffffffffull)); }
__device__ __forceinline__ float hi_f(unsigned long long p) { return __uint_as_float((unsigned)(p >> 32)); }

#define FMA2(d, a, b, c) asm("fma.rn.f32x2 %0, %1, %2, %3;" : "=l"(d) : "l"(a), "l"(b), "l"(c))

// ---------------- zero scratch ----------------
__global__ void zero_kernel() {
    long t0 = (long)blockIdx.x * blockDim.x + threadIdx.x;
    long stride = (long)gridDim.x * blockDim.x;
    for (long i = t0; i < (long)NN * DD; i += stride) g_node_agg[i] = 0.f;
    for (long i = t0; i < (long)NN * 24; i += stride) g_coord_sum[i] = 0.f;
    for (long i = t0; i < NN; i += stride) g_cnt[i] = 0.f;
    if (t0 == 0) g_maxbits = 0u;
}

// ---------------- weight pre-packing (K-pair interleave) ----------------
__global__ void pack_kernel(const float* __restrict__ m_w1,
                            const float* __restrict__ m_w2,
                            const float* __restrict__ c_w1,
                            const float* __restrict__ c_w2,
                            const float* __restrict__ het_w) {
    int t0 = blockIdx.x * blockDim.x + threadIdx.x;
    int stride = gridDim.x * blockDim.x;
    for (int i = t0; i < 128 * 128; i += stride) {
        int kp = i >> 7, j = i & 127;
        g_W1p[i] = packf2(m_w1[(2 * kp) * 128 + j], m_w1[(2 * kp + 1) * 128 + j]);
    }
    for (int i = t0; i < 64 * 128; i += stride) {
        int kp = i >> 7, j = i & 127;
        g_W2p[i]  = packf2(m_w2[(2 * kp) * 128 + j],  m_w2[(2 * kp + 1) * 128 + j]);
        g_CW1p[i] = packf2(c_w1[(2 * kp) * 128 + j],  c_w1[(2 * kp + 1) * 128 + j]);
        g_HWp[i]  = packf2(het_w[(2 * kp) * 128 + j], het_w[(2 * kp + 1) * 128 + j]);
    }
    for (int i = t0; i < 64 * 8; i += stride) {
        int kp = i >> 3, j = i & 7;
        g_CW2p[i] = packf2(c_w2[(2 * kp) * 8 + j], c_w2[(2 * kp + 1) * 8 + j]);
    }
}

// ---------------- per-node precompute: csum, pooled_col ----------------
__global__ void node_pre_kernel(const float* __restrict__ coords,
                                const float* __restrict__ cw) {
    int n = blockIdx.x * blockDim.x + threadIdx.x;
    if (n >= NN) return;
    float px = 0.f, py = 0.f, pz = 0.f;
    int cs = 0;
#pragma unroll
    for (int c = 0; c < 8; c++) {
        float w = cw[n * 8 + c];
        if (w != 0.f) {
            cs++;
            px += coords[n * 24 + c * 3 + 0];
            py += coords[n * 24 + c * 3 + 1];
            pz += coords[n * 24 + c * 3 + 2];
        }
    }
    float inv = 1.f / ((float)cs + 0.001f);
    g_pcol[n * 3 + 0] = px * inv;
    g_pcol[n * 3 + 1] = py * inv;
    g_pcol[n * 3 + 2] = pz * inv;
    g_csum[n] = cs;
}

// ---------------- global max of squared channel distances ----------------
__global__ void max_kernel(const float* __restrict__ coords,
                           const int* __restrict__ el) {
    int e = blockIdx.x * blockDim.x + threadIdx.x;
    float m = 0.f;
    if (e < EE) {
        int src = el[e * 3 + 0];
        int tgt = el[e * 3 + 1];
        float ct[24], cs[24];
#pragma unroll
        for (int i = 0; i < 24; i++) {
            ct[i] = coords[(long)tgt * 24 + i];
            cs[i] = coords[(long)src * 24 + i];
        }
#pragma unroll
        for (int c = 0; c < 8; c++) {
#pragma unroll
            for (int d = 0; d < 8; d++) {
                float dx = ct[c * 3 + 0] - cs[d * 3 + 0];
                float dy = ct[c * 3 + 1] - cs[d * 3 + 1];
                float dz = ct[c * 3 + 2] - cs[d * 3 + 2];
                float ns = dx * dx + dy * dy + dz * dz;
                m = fmaxf(m, ns);
            }
        }
    }
#pragma unroll
    for (int o = 16; o > 0; o >>= 1)
        m = fmaxf(m, __shfl_xor_sync(0xffffffffu, m, o));
    if ((threadIdx.x & 31) == 0)
        atomicMax(&g_maxbits, __float_as_uint(m));  // valid for non-negative floats
}

// ---------------- per-node GEMM: Ah = h@W1a, Bh = h@W1b ----------------
__global__ __launch_bounds__(NTHR, 3)
void node_gemm_kernel(const float* __restrict__ h) {
    __shared__ __align__(16) float hs[32 * MS];
    const int tid = threadIdx.x;
    const int base = blockIdx.x * 32;

    for (int idx = tid; idx < 32 * 128; idx += NTHR) {
        int n = idx >> 7, k = idx & 127;
        int gn = base + n;
        hs[n * MS + k] = (gn < NN) ? h[(long)gn * 128 + k] : 0.f;
    }
    __syncthreads();

    const int cg = tid & 63;
    const int ng = tid >> 6;
#pragma unroll
    for (int half = 0; half < 2; half++) {
        float* dst = half ? g_Bh : g_Ah;
        const ulonglong2* Wv = (const ulonglong2*)(g_W1p + half * 64 * 128);
        unsigned long long acc0[8], acc1[8];
#pragma unroll
        for (int r = 0; r < 8; r++) { acc0[r] = 0ull; acc1[r] = 0ull; }
#pragma unroll 2
        for (int kp2 = 0; kp2 < 32; kp2++) {
            ulonglong2 wa = Wv[(2 * kp2 + 0) * 64 + cg];
            ulonglong2 wb = Wv[(2 * kp2 + 1) * 64 + cg];
#pragma unroll
            for (int r = 0; r < 8; r++) {
                ulonglong2 xv = *(const ulonglong2*)&hs[(ng * 8 + r) * MS + kp2 * 4];
                FMA2(acc0[r], xv.x, wa.x, acc0[r]);
                FMA2(acc1[r], xv.x, wa.y, acc1[r]);
                FMA2(acc0[r], xv.y, wb.x, acc0[r]);
                FMA2(acc1[r], xv.y, wb.y, acc1[r]);
            }
        }
#pragma unroll
        for (int r = 0; r < 8; r++) {
            int gn = base + ng * 8 + r;
            if (gn < NN) {
                float2 o;
                o.x = lo_f(acc0[r]) + hi_f(acc0[r]);
                o.y = lo_f(acc1[r]) + hi_f(acc1[r]);
                *(float2*)&dst[(long)gn * 128 + cg * 2] = o;
            }
        }
    }
}

// ---------------- edge preprocessing: one edge per warp ----------------
__global__ __launch_bounds__(256)
void edge_pre_kernel(const float* __restrict__ coords,
                     const float* __restrict__ ca,
                     const float* __restrict__ cw,
                     const float* __restrict__ edge_weights,
                     const int* __restrict__ el,
                     const float* __restrict__ rl_w,
                     const float* __restrict__ rl_b,
                     const float* __restrict__ w_r) {
    __shared__ float wscr[8][320];
    const int wid = threadIdx.x >> 5;
    const int lane = threadIdx.x & 31;
    const long ge = (long)blockIdx.x * 8 + wid;
    if (ge >= (long)EE) return;

    float gmax = sqrtf(__uint_as_float(g_maxbits));
    float inv_g = 1.f / (gmax + 0.001f);

    float* WS  = &wscr[wid][0];
    float* At  = WS;
    float* Bs  = WS + 64;
    float* Mm  = WS + 128;
    float* Tt  = WS + 192;
    float* cwt = WS + 256;
    float* cws = WS + 264;
    float* ctb = WS + 272;
    float* csb = WS + 296;

    int src = el[ge * 3 + 0];
    int tgt = el[ge * 3 + 1];
    int rel = el[ge * 3 + 2];

    At[lane]      = ca[(long)tgt * 64 + lane];
    At[lane + 32] = ca[(long)tgt * 64 + lane + 32];
    Bs[lane]      = ca[(long)src * 64 + lane];
    Bs[lane + 32] = ca[(long)src * 64 + lane + 32];
    if (lane < 8) { cwt[lane] = cw[(long)tgt * 8 + lane]; cws[lane] = cw[(long)src * 8 + lane]; }
    if (lane < 24) { ctb[lane] = coords[(long)tgt * 24 + lane]; csb[lane] = coords[(long)src * 24 + lane]; }
    __syncwarp();

    // M[c][d] = (||ct_c - cs_d|| / (gmax+eps)) * cwt[c]*cws[d]
#pragma unroll
    for (int half = 0; half < 2; half++) {
        int idx = lane + half * 32;
        int c = idx >> 3, d = idx & 7;
        float dx = ctb[c * 3 + 0] - csb[d * 3 + 0];
        float dy = ctb[c * 3 + 1] - csb[d * 3 + 1];
        float dz = ctb[c * 3 + 2] - csb[d * 3 + 2];
        float ns = dx * dx + dy * dy + dz * dz;
        float nrm = (ns > 0.f) ? ns * rsqrtf(ns) : 0.f;
        Mm[idx] = nrm * inv_g * cwt[c] * cws[d];
    }
    __syncwarp();

    // T[a][d] = sum_c At[c][a] * M[c][d]
#pragma unroll
    for (int half = 0; half < 2; half++) {
        int idx = lane + half * 32;
        int a = idx >> 3, d = idx & 7;
        float t = 0.f;
#pragma unroll
        for (int c = 0; c < 8; c++) t = fmaf(At[c * 8 + a], Mm[c * 8 + d], t);
        Tt[idx] = t;
    }
    __syncwarp();

    // R[a][b] = sum_d T[a][d] * Bs[d][b]
    float r0 = 0.f, r1 = 0.f;
    {
        int a = lane >> 3, b = lane & 7;
#pragma unroll
        for (int d = 0; d < 8; d++) r0 = fmaf(Tt[a * 8 + d], Bs[d * 8 + b], r0);
        int idx = lane + 32;
        a = idx >> 3; b = idx & 7;
#pragma unroll
        for (int d = 0; d < 8; d++) r1 = fmaf(Tt[a * 8 + d], Bs[d * 8 + b], r1);
    }
    float ss = r0 * r0 + r1 * r1;
#pragma unroll
    for (int o = 16; o > 0; o >>= 1) ss += __shfl_xor_sync(0xffffffffu, ss, o);
    float invn = 1.f / (sqrtf(ss) + 0.001f);
    Mm[lane] = r0;           // reuse M as flattened R
    Mm[lane + 32] = r1;
    __syncwarp();

    // radial_out[j] = (R . rl_w[:,j]) * invn + rl_b[j]
    if (lane < 8) {
        float acc = 0.f;
#pragma unroll
        for (int k = 0; k < 64; k++) acc = fmaf(Mm[k], rl_w[k * 8 + lane], acc);
        g_rad[ge * 8 + lane] = acc * invn + rl_b[lane];
    }
    // coord_diff = coords[tgt] - pooled_col[src]
    if (lane < 24) {
        int k = lane % 3;
        g_cdiff[ge * 24 + lane] = ctb[lane] - g_pcol[(long)src * 3 + k];
    }
    if (lane == 0) {
        int cs = g_csum[tgt];
        int ts = cs - 1;
        ts = ts < 0 ? 0 : (ts > 7 ? 7 : ts);
        g_meta[ge] = make_int4(tgt, src, ts, __float_as_int(edge_weights[ge]));
        g_wr[ge] = w_r[rel];
    }
}

// ---------------- fused edge GEMM kernel ----------------
struct __align__(16) EdgeSmem {
    float ms1[TILE_E * MS];    // m1 / cf reuse (16B-aligned: MS*4=528 % 16 == 0)
    float ms2[TILE_E * MS];    // m (post-GEMM2)
    float w1c[8 * 128];        // m_w1 rows 256..263 (radial part)
    float b1s[128];
    float rad[TILE_E * 8];
    float ef[TILE_E * 8];
    int   s_tgt[TILE_E];
    int   s_src[TILE_E];
    float s_ew[TILE_E];
    float s_wr[TILE_E];
    int   s_ts[TILE_E];
};

// 32 (edges) x 128 (cols) GEMM with packed-K FFMA2; LDS.128 reads 2 kp at once.
// 256 threads: eg = tid>>6 (4 groups of 8 edges), cg = tid&63 (64 col-pairs).
template <int KP2>
__device__ __forceinline__ void tile_gemm(const float* __restrict__ src, int sstride,
                                          const unsigned long long* __restrict__ Wp,
                                          const float* __restrict__ bias,
                                          float* __restrict__ dst, int tid) {
    const int cg = tid & 63;
    const int eg = tid >> 6;
    unsigned long long acc0[8], acc1[8];
#pragma unroll
    for (int r = 0; r < 8; r++) { acc0[r] = 0ull; acc1[r] = 0ull; }

    const ulonglong2* Wv = (const ulonglong2*)Wp;  // [2*KP2][64] of ulonglong2
    const float* srow = &src[eg * 8 * sstride];
#pragma unroll 2
    for (int kp2 = 0; kp2 < KP2; kp2++) {
        ulonglong2 wa = Wv[(2 * kp2 + 0) * 64 + cg];
        ulonglong2 wb = Wv[(2 * kp2 + 1) * 64 + cg];
#pragma unroll
        for (int r = 0; r < 8; r++) {
            ulonglong2 xv = *(const ulonglong2*)&srow[r * sstride + kp2 * 4];
            FMA2(acc0[r], xv.x, wa.x, acc0[r]);
            FMA2(acc1[r], xv.x, wa.y, acc1[r]);
            FMA2(acc0[r], xv.y, wb.x, acc0[r]);
            FMA2(acc1[r], xv.y, wb.y, acc1[r]);
        }
    }
    float2 bb = *(const float2*)&bias[cg * 2];
#pragma unroll
    for (int r = 0; r < 8; r++) {
        float2 o;
        o.x = silu_f(lo_f(acc0[r]) + hi_f(acc0[r]) + bb.x);
        o.y = silu_f(lo_f(acc1[r]) + hi_f(acc1[r]) + bb.y);
        *(float2*)&dst[(eg * 8 + r) * MS + cg * 2] = o;
    }
}

__global__ __launch_bounds__(NTHR, 3)
void edge_kernel(const float* __restrict__ m_w1,
                 const float* __restrict__ m_b1,
                 const float* __restrict__ m_b2,
                 const float* __restrict__ c_b1) {
    extern __shared__ char smem_raw[];
    EdgeSmem& sm = *reinterpret_cast<EdgeSmem*>(smem_raw);

    const int tid = threadIdx.x;
    const long tileBase = (long)blockIdx.x * TILE_E;

    // stage W1c (radial rows) + b1
    for (int i = tid; i < 8 * 128; i += NTHR) sm.w1c[i] = m_w1[256 * 128 + i];
    if (tid < 128) sm.b1s[tid] = m_b1[tid];

    // load meta + rad (coalesced; EE is an exact multiple of TILE_E)
    if (tid < TILE_E) {
        long ge = tileBase + tid;
        int4 m = g_meta[ge];
        sm.s_tgt[tid] = m.x;
        sm.s_src[tid] = m.y;
        sm.s_ts[tid]  = m.z;
        sm.s_ew[tid]  = __int_as_float(m.w);
        sm.s_wr[tid]  = g_wr[ge];
    }
    if (tid < TILE_E * 8)
        sm.rad[tid] = g_rad[tileBase * 8 + tid];
    __syncthreads();

    // ---- m1 = silu(Ah[tgt] + Bh[src] + rad @ W1c + b1) ----
    {
        const int e = tid >> 3;          // 32 edges
        const int q = tid & 7;           // 8 col-quarters of 16
        const int j0 = q * 16;
        int t = sm.s_tgt[e];
        int s = sm.s_src[e];
        float r[8];
#pragma unroll
        for (int k = 0; k < 8; k++) r[k] = sm.rad[e * 8 + k];
#pragma unroll
        for (int v = 0; v < 4; v++) {
            int j = j0 + v * 4;
            float4 a  = *(const float4*)&g_Ah[(long)t * 128 + j];
            float4 b  = *(const float4*)&g_Bh[(long)s * 128 + j];
            float4 bb = *(const float4*)&sm.b1s[j];
            float4 acc;
            acc.x = a.x + b.x + bb.x;
            acc.y = a.y + b.y + bb.y;
            acc.z = a.z + b.z + bb.z;
            acc.w = a.w + b.w + bb.w;
#pragma unroll
            for (int k = 0; k < 8; k++) {
                float4 w = *(const float4*)&sm.w1c[k * 128 + j];
                acc.x = fmaf(r[k], w.x, acc.x);
                acc.y = fmaf(r[k], w.y, acc.y);
                acc.z = fmaf(r[k], w.z, acc.z);
                acc.w = fmaf(r[k], w.w, acc.w);
            }
            float4 o;
            o.x = silu_f(acc.x); o.y = silu_f(acc.y);
            o.z = silu_f(acc.z); o.w = silu_f(acc.w);
            *(float4*)&sm.ms1[e * MS + j] = o;
        }
    }
    __syncthreads();

    // ---- GEMM chain (packed-K FFMA2, LDS.128, 8 rows x 2 cols per thread) ----
    tile_gemm<32>(sm.ms1, MS, g_W2p,  m_b2, sm.ms2, tid);   // m  = silu(m1@W2+b2)
    __syncthreads();
    tile_gemm<32>(sm.ms2, MS, g_CW1p, c_b1, sm.ms1, tid);   // cf = silu(m@Cw1+Cb1)
    __syncthreads();

    // edge_feat = cf @ c_w2  (32 edges x 8), packed-K, LDS.128
    {
        int e = tid >> 3;
        int j = tid & 7;
        unsigned long long acc = 0ull;
#pragma unroll 4
        for (int kp2 = 0; kp2 < 32; kp2++) {
            ulonglong2 cf = *(const ulonglong2*)&sm.ms1[e * MS + kp2 * 4];
            FMA2(acc, cf.x, g_CW2p[(2 * kp2 + 0) * 8 + j], acc);
            FMA2(acc, cf.y, g_CW2p[(2 * kp2 + 1) * 8 + j], acc);
        }
        sm.ef[e * 8 + j] = lo_f(acc) + hi_f(acc);
    }
    __syncthreads();

    // ---- aggregation atomics ----
    // node_agg[tgt] += m * ew
    for (int idx = tid; idx < TILE_E * 128; idx += NTHR) {
        int e = idx >> 7, j = idx & 127;
        int t = sm.s_tgt[e];
        atomicAdd(&g_node_agg[(long)t * 128 + j], sm.ms2[e * MS + j] * sm.s_ew[e]);
    }
    // coord_sum[tgt] += w_r * coord_diff * pooled_edge
    if (tid < TILE_E * 8) {
        int e = tid >> 3, a = tid & 7;
        int t = sm.s_tgt[e];
        int ts = sm.s_ts[e];
        int w = 8 - ts;
        int hi = a + w; if (hi > 8) hi = 8;
        float s = 0.f;
        for (int b = a; b < hi; b++) s += sm.ef[e * 8 + b];
        float pe = (s / (float)w) * sm.s_wr[e];
        long ge = tileBase + e;
#pragma unroll
        for (int k = 0; k < 3; k++)
            atomicAdd(&g_coord_sum[(long)t * 24 + a * 3 + k],
                      g_cdiff[ge * 24 + a * 3 + k] * pe);
    }
    // cnt[tgt] += 1
    if (tid < TILE_E) {
        atomicAdd(&g_cnt[sm.s_tgt[tid]], 1.f);
    }
}

// ---------------- node epilogue: out GEMM + BN + silu + residuals ----------------
__global__ __launch_bounds__(NTHR, 3)
void node_out_kernel(const float* __restrict__ h,
                     const float* __restrict__ coords,
                     const float* __restrict__ het_b,
                     const float* __restrict__ gamma,
                     const float* __restrict__ beta,
                     float* __restrict__ out) {
    __shared__ __align__(16) float ag[32 * MS];
    const int tid = threadIdx.x;
    const int base = blockIdx.x * 32;
    const float INVS = 0.9999950000374996f;  // 1/sqrt(1+1e-5)

    for (int idx = tid; idx < 32 * 128; idx += NTHR) {
        int n = idx >> 7, k = idx & 127;
        int gn = base + n;
        ag[n * MS + k] = (gn < NN) ? g_node_agg[(long)gn * 128 + k] : 0.f;
    }
    __syncthreads();

    const int cg = tid & 63;
    const int ng = tid >> 6;
    unsigned long long acc0[8], acc1[8];
#pragma unroll
    for (int r = 0; r < 8; r++) { acc0[r] = 0ull; acc1[r] = 0ull; }
    const ulonglong2* Wv = (const ulonglong2*)g_HWp;
#pragma unroll 2
    for (int kp2 = 0; kp2 < 32; kp2++) {
        ulonglong2 wa = Wv[(2 * kp2 + 0) * 64 + cg];
        ulonglong2 wb = Wv[(2 * kp2 + 1) * 64 + cg];
#pragma unroll
        for (int r = 0; r < 8; r++) {
            ulonglong2 xv = *(const ulonglong2*)&ag[(ng * 8 + r) * MS + kp2 * 4];
            FMA2(acc0[r], xv.x, wa.x, acc0[r]);
            FMA2(acc1[r], xv.x, wa.y, acc1[r]);
            FMA2(acc0[r], xv.y, wb.x, acc0[r]);
            FMA2(acc1[r], xv.y, wb.y, acc1[r]);
        }
    }
    int j0 = cg * 2;
    float2 hb = *(const float2*)&het_b[j0];
    float2 gm = *(const float2*)&gamma[j0];
    float2 bt = *(const float2*)&beta[j0];
#pragma unroll
    for (int r = 0; r < 8; r++) {
        int gn = base + ng * 8 + r;
        if (gn < NN) {
            float2 o;
            o.x = silu_f((lo_f(acc0[r]) + hi_f(acc0[r]) + hb.x) * INVS * gm.x + bt.x);
            o.y = silu_f((lo_f(acc1[r]) + hi_f(acc1[r]) + hb.y) * INVS * gm.y + bt.y);
            float2 hv = *(const float2*)&h[(long)gn * 128 + j0];
            o.x += hv.x; o.y += hv.y;
            *(float2*)&out[(long)gn * 128 + j0] = o;
        }
    }

    // coord_output = coords + coord_sum / max(cnt,1)
    for (int idx = tid; idx < 32 * 24; idx += NTHR) {
        int n = idx / 24, k = idx % 24;
        int gn = base + n;
        if (gn < NN) {
            float c = fmaxf(g_cnt[gn], 1.f);
            out[(long)NN * 128 + (long)gn * 24 + k] =
                coords[(long)gn * 24 + k] + g_coord_sum[(long)gn * 24 + k] / c;
        }
    }
}

// ---------------- launch ----------------
extern "C" void kernel_launch(void* const* d_in, const int* in_sizes, int n_in,
                              void* d_out, int out_size) {
    (void)in_sizes; (void)n_in; (void)out_size;
    const float* h      = (const float*)d_in[0];
    const float* coords = (const float*)d_in[1];
    const float* ca     = (const float*)d_in[2];
    const float* cw     = (const float*)d_in[3];
    const float* ew     = (const float*)d_in[4];
    const int*   el     = (const int*)d_in[5];
    const float* rl_w   = (const float*)d_in[6];
    const float* rl_b   = (const float*)d_in[7];
    const float* m_w1   = (const float*)d_in[8];
    const float* m_b1   = (const float*)d_in[9];
    const float* m_w2   = (const float*)d_in[10];
    const float* m_b2   = (const float*)d_in[11];
    const float* c_w1   = (const float*)d_in[12];
    const float* c_b1   = (const float*)d_in[13];
    const float* c_w2   = (const float*)d_in[14];
    const float* het_w  = (const float*)d_in[15];
    const float* het_b  = (const float*)d_in[16];
    const float* gamma  = (const float*)d_in[17];
    const float* beta   = (const float*)d_in[18];
    const float* w_r    = (const float*)d_in[19];
    float* out = (float*)d_out;

    cudaFuncSetAttribute(edge_kernel, cudaFuncAttributeMaxDynamicSharedMemorySize,
                         (int)sizeof(EdgeSmem));

    zero_kernel<<<2048, 256>>>();
    pack_kernel<<<132, 256>>>(m_w1, m_w2, c_w1, c_w2, het_w);
    node_pre_kernel<<<(NN + 255) / 256, 256>>>(coords, cw);
    node_gemm_kernel<<<(NN + 31) / 32, NTHR>>>(h);
    max_kernel<<<(EE + 255) / 256, 256>>>(coords, el);
    edge_pre_kernel<<<(EE + 7) / 8, 256>>>(coords, ca, cw, ew, el, rl_w, rl_b, w_r);
    edge_kernel<<<EE / TILE_E, NTHR, sizeof(EdgeSmem)>>>(m_w1, m_b1, m_b2, c_b1);
    node_out_kernel<<<(NN + 31) / 32, NTHR>>>(h, coords, het_b, gamma, beta, out);
}

// round 10
// speedup vs baseline: 1.4531x; 1.4531x over previous
#include <cuda_runtime.h>
#include <math.h>

#define NN 50000
#define EE 400000
#define DD 128
#define CC 8

#define TILE_E 32
#define NTHR 256
#define MS 132   // row stride in floats (128 used, 16B-aligned rows)

typedef unsigned long long ull;

// ---------------- device scratch (no allocations allowed) ----------------
__device__ float g_node_agg[NN * DD];        // 25.6 MB
__device__ float g_coord_sum[NN * CC * 3];   // 4.8 MB
__device__ float g_cnt[NN];
__device__ float g_pcol[NN * 3];
__device__ int   g_csum[NN];
__device__ unsigned int g_maxbits;
__device__ float g_Ah[NN * DD];              // h @ W1[:128]
__device__ float g_Bh[NN * DD];              // h @ W1[128:256]

// edge-pre outputs
__device__ float g_rad[EE * 8];              // radial MLP output
__device__ float g_cdiff[EE * 24];           // coord_diff
__device__ int4  g_meta[EE];                 // {tgt, src, ts, ew_bits}
__device__ float g_wr[EE];

// K-pair-interleaved packed weights: [kp*COLS + j] = pack(w[2kp][j], w[2kp+1][j])
__device__ ull g_W1p[128 * 128];   // m_w1 rows 0..255
__device__ ull g_W2p[64 * 128];    // m_w2
__device__ ull g_CW1p[64 * 128];   // c_w1
__device__ ull g_HWp[64 * 128];    // het_w
__device__ ull g_CW2p[64 * 8];     // c_w2

__device__ __forceinline__ float silu_f(float x) {
    return x * (1.0f / (1.0f + __expf(-x)));
}
__device__ __forceinline__ ull packf2(float lo, float hi) {
    return ((ull)__float_as_uint(hi) << 32) | (ull)__float_as_uint(lo);
}
__device__ __forceinline__ float lo_f(ull p) { return __uint_as_float((unsigned)(p & 0xffffffffull)); }
__device__ __forceinline__ float hi_f(ull p) { return __uint_as_float((unsigned)(p >> 32)); }

#define FMA2(d, a, b, c) asm("fma.rn.f32x2 %0, %1, %2, %3;" : "=l"(d) : "l"(a), "l"(b), "l"(c))

// ---------------- zero scratch ----------------
__global__ void zero_kernel() {
    long t0 = (long)blockIdx.x * blockDim.x + threadIdx.x;
    long stride = (long)gridDim.x * blockDim.x;
    for (long i = t0; i < (long)NN * DD; i += stride) g_node_agg[i] = 0.f;
    for (long i = t0; i < (long)NN * 24; i += stride) g_coord_sum[i] = 0.f;
    for (long i = t0; i < NN; i += stride) g_cnt[i] = 0.f;
    if (t0 == 0) g_maxbits = 0u;
}

// ---------------- weight pre-packing ----------------
__global__ void pack_kernel(const float* __restrict__ m_w1,
                            const float* __restrict__ m_w2,
                            const float* __restrict__ c_w1,
                            const float* __restrict__ c_w2,
                            const float* __restrict__ het_w) {
    int t0 = blockIdx.x * blockDim.x + threadIdx.x;
    int stride = gridDim.x * blockDim.x;
    for (int i = t0; i < 128 * 128; i += stride) {
        int kp = i >> 7, j = i & 127;
        g_W1p[i] = packf2(m_w1[(2 * kp) * 128 + j], m_w1[(2 * kp + 1) * 128 + j]);
    }
    for (int i = t0; i < 64 * 128; i += stride) {
        int kp = i >> 7, j = i & 127;
        g_W2p[i]  = packf2(m_w2[(2 * kp) * 128 + j],  m_w2[(2 * kp + 1) * 128 + j]);
        g_CW1p[i] = packf2(c_w1[(2 * kp) * 128 + j],  c_w1[(2 * kp + 1) * 128 + j]);
        g_HWp[i]  = packf2(het_w[(2 * kp) * 128 + j], het_w[(2 * kp + 1) * 128 + j]);
    }
    for (int i = t0; i < 64 * 8; i += stride) {
        int kp = i >> 3, j = i & 7;
        g_CW2p[i] = packf2(c_w2[(2 * kp) * 8 + j], c_w2[(2 * kp + 1) * 8 + j]);
    }
}

// ---------------- per-node precompute: csum, pooled_col ----------------
__global__ void node_pre_kernel(const float* __restrict__ coords,
                                const float* __restrict__ cw) {
    int n = blockIdx.x * blockDim.x + threadIdx.x;
    if (n >= NN) return;
    float px = 0.f, py = 0.f, pz = 0.f;
    int cs = 0;
#pragma unroll
    for (int c = 0; c < 8; c++) {
        float w = cw[n * 8 + c];
        if (w != 0.f) {
            cs++;
            px += coords[n * 24 + c * 3 + 0];
            py += coords[n * 24 + c * 3 + 1];
            pz += coords[n * 24 + c * 3 + 2];
        }
    }
    float inv = 1.f / ((float)cs + 0.001f);
    g_pcol[n * 3 + 0] = px * inv;
    g_pcol[n * 3 + 1] = py * inv;
    g_pcol[n * 3 + 2] = pz * inv;
    g_csum[n] = cs;
}

// ---------------- global max of squared channel distances ----------------
__global__ void max_kernel(const float* __restrict__ coords,
                           const int* __restrict__ el) {
    int e = blockIdx.x * blockDim.x + threadIdx.x;
    float m = 0.f;
    if (e < EE) {
        int src = el[e * 3 + 0];
        int tgt = el[e * 3 + 1];
        float ct[24], cs[24];
#pragma unroll
        for (int i = 0; i < 24; i++) {
            ct[i] = coords[(long)tgt * 24 + i];
            cs[i] = coords[(long)src * 24 + i];
        }
#pragma unroll
        for (int c = 0; c < 8; c++) {
#pragma unroll
            for (int d = 0; d < 8; d++) {
                float dx = ct[c * 3 + 0] - cs[d * 3 + 0];
                float dy = ct[c * 3 + 1] - cs[d * 3 + 1];
                float dz = ct[c * 3 + 2] - cs[d * 3 + 2];
                float ns = dx * dx + dy * dy + dz * dz;
                m = fmaxf(m, ns);
            }
        }
    }
#pragma unroll
    for (int o = 16; o > 0; o >>= 1)
        m = fmaxf(m, __shfl_xor_sync(0xffffffffu, m, o));
    if ((threadIdx.x & 31) == 0)
        atomicMax(&g_maxbits, __float_as_uint(m));
}

// ---------------- per-node GEMM: Ah = h@W1a, Bh = h@W1b  (R6 version) ----------------
__global__ __launch_bounds__(NTHR, 3)
void node_gemm_kernel(const float* __restrict__ h) {
    __shared__ float hs[32 * MS];
    const int tid = threadIdx.x;
    const int base = blockIdx.x * 32;

    for (int idx = tid; idx < 32 * 128; idx += NTHR) {
        int n = idx >> 7, k = idx & 127;
        int gn = base + n;
        hs[n * MS + k] = (gn < NN) ? h[(long)gn * 128 + k] : 0.f;
    }
    __syncthreads();

    const int cg = tid & 63;
    const int ng = tid >> 6;
#pragma unroll
    for (int half = 0; half < 2; half++) {
        float* dst = half ? g_Bh : g_Ah;
        const ulonglong2* Wv = (const ulonglong2*)(g_W1p + half * 64 * 128);
        ull acc0[8], acc1[8];
#pragma unroll
        for (int r = 0; r < 8; r++) { acc0[r] = 0ull; acc1[r] = 0ull; }
#pragma unroll 4
        for (int kp = 0; kp < 64; kp++) {
            ulonglong2 w = Wv[kp * 64 + cg];
#pragma unroll
            for (int r = 0; r < 8; r++) {
                ull xv = *(const ull*)&hs[(ng * 8 + r) * MS + kp * 2];
                FMA2(acc0[r], xv, w.x, acc0[r]);
                FMA2(acc1[r], xv, w.y, acc1[r]);
            }
        }
#pragma unroll
        for (int r = 0; r < 8; r++) {
            int gn = base + ng * 8 + r;
            if (gn < NN) {
                float2 o;
                o.x = lo_f(acc0[r]) + hi_f(acc0[r]);
                o.y = lo_f(acc1[r]) + hi_f(acc1[r]);
                *(float2*)&dst[(long)gn * 128 + cg * 2] = o;
            }
        }
    }
}

// ---------------- edge preprocessing: one edge per warp (R6 version) ----------------
__global__ __launch_bounds__(256)
void edge_pre_kernel(const float* __restrict__ coords,
                     const float* __restrict__ ca,
                     const float* __restrict__ cw,
                     const float* __restrict__ edge_weights,
                     const int* __restrict__ el,
                     const float* __restrict__ rl_w,
                     const float* __restrict__ rl_b,
                     const float* __restrict__ w_r) {
    __shared__ float wscr[8][320];
    const int wid = threadIdx.x >> 5;
    const int lane = threadIdx.x & 31;
    const long ge = (long)blockIdx.x * 8 + wid;
    if (ge >= (long)EE) return;

    float gmax = sqrtf(__uint_as_float(g_maxbits));
    float inv_g = 1.f / (gmax + 0.001f);

    float* WS  = &wscr[wid][0];
    float* At  = WS;
    float* Bs  = WS + 64;
    float* Mm  = WS + 128;
    float* Tt  = WS + 192;
    float* cwt = WS + 256;
    float* cws = WS + 264;
    float* ctb = WS + 272;
    float* csb = WS + 296;

    int src = el[ge * 3 + 0];
    int tgt = el[ge * 3 + 1];
    int rel = el[ge * 3 + 2];

    At[lane]      = ca[(long)tgt * 64 + lane];
    At[lane + 32] = ca[(long)tgt * 64 + lane + 32];
    Bs[lane]      = ca[(long)src * 64 + lane];
    Bs[lane + 32] = ca[(long)src * 64 + lane + 32];
    if (lane < 8) { cwt[lane] = cw[(long)tgt * 8 + lane]; cws[lane] = cw[(long)src * 8 + lane]; }
    if (lane < 24) { ctb[lane] = coords[(long)tgt * 24 + lane]; csb[lane] = coords[(long)src * 24 + lane]; }
    __syncwarp();

#pragma unroll
    for (int half = 0; half < 2; half++) {
        int idx = lane + half * 32;
        int c = idx >> 3, d = idx & 7;
        float dx = ctb[c * 3 + 0] - csb[d * 3 + 0];
        float dy = ctb[c * 3 + 1] - csb[d * 3 + 1];
        float dz = ctb[c * 3 + 2] - csb[d * 3 + 2];
        float ns = dx * dx + dy * dy + dz * dz;
        float nrm = (ns > 0.f) ? ns * rsqrtf(ns) : 0.f;
        Mm[idx] = nrm * inv_g * cwt[c] * cws[d];
    }
    __syncwarp();

#pragma unroll
    for (int half = 0; half < 2; half++) {
        int idx = lane + half * 32;
        int a = idx >> 3, d = idx & 7;
        float t = 0.f;
#pragma unroll
        for (int c = 0; c < 8; c++) t = fmaf(At[c * 8 + a], Mm[c * 8 + d], t);
        Tt[idx] = t;
    }
    __syncwarp();

    float r0 = 0.f, r1 = 0.f;
    {
        int a = lane >> 3, b = lane & 7;
#pragma unroll
        for (int d = 0; d < 8; d++) r0 = fmaf(Tt[a * 8 + d], Bs[d * 8 + b], r0);
        int idx = lane + 32;
        a = idx >> 3; b = idx & 7;
#pragma unroll
        for (int d = 0; d < 8; d++) r1 = fmaf(Tt[a * 8 + d], Bs[d * 8 + b], r1);
    }
    float ss = r0 * r0 + r1 * r1;
#pragma unroll
    for (int o = 16; o > 0; o >>= 1) ss += __shfl_xor_sync(0xffffffffu, ss, o);
    float invn = 1.f / (sqrtf(ss) + 0.001f);
    Mm[lane] = r0;
    Mm[lane + 32] = r1;
    __syncwarp();

    if (lane < 8) {
        float acc = 0.f;
#pragma unroll
        for (int k = 0; k < 64; k++) acc = fmaf(Mm[k], rl_w[k * 8 + lane], acc);
        g_rad[ge * 8 + lane] = acc * invn + rl_b[lane];
    }
    if (lane < 24) {
        int k = lane % 3;
        g_cdiff[ge * 24 + lane] = ctb[lane] - g_pcol[(long)src * 3 + k];
    }
    if (lane == 0) {
        int cs = g_csum[tgt];
        int ts = cs - 1;
        ts = ts < 0 ? 0 : (ts > 7 ? 7 : ts);
        g_meta[ge] = make_int4(tgt, src, ts, __float_as_int(edge_weights[ge]));
        g_wr[ge] = w_r[rel];
    }
}

// ---------------- fused edge GEMM kernel (K-pair-major intermediates) ----------------
struct __align__(16) EdgeSmem {
    ull   mt1[64 * 32];        // activations, [kp][edge] packed u64 (16 KB)
    ull   mt2[64 * 32];        // (16 KB)
    float ms2[TILE_E * MS];    // m in row format for node_agg atomics
    float w1c[8 * 128];        // m_w1 rows 256..263
    float b1s[128];
    float rad[TILE_E * 8];
    float ef[TILE_E * 8];
    int   s_tgt[TILE_E];
    int   s_src[TILE_E];
    float s_ew[TILE_E];
    float s_wr[TILE_E];
    int   s_ts[TILE_E];
};

// 32x128 GEMM, inputs/outputs in [kp][edge] u64 format.
// Warp w: cols [16w,16w+16). Lane: eq = l&7 (edge base), cq = l>>3 (4-col group).
// Thread: edges {eq, eq+8, eq+16, eq+24} x cols {j0..j0+3}, j0 = 16w + 4cq.
template <bool WRITE_ROWS>
__device__ __forceinline__ void tile_gemm_t(const ull* __restrict__ mt_in,
                                            const ull* __restrict__ Wp,
                                            const float* __restrict__ bias,
                                            ull* __restrict__ mt_out,
                                            float* __restrict__ rows_out,
                                            int tid) {
    const int w  = tid >> 5;
    const int l  = tid & 31;
    const int eq = l & 7;
    const int cq = l >> 3;
    const int j0 = 16 * w + 4 * cq;

    ull acc[4][4];
#pragma unroll
    for (int r = 0; r < 4; r++)
#pragma unroll
        for (int c = 0; c < 4; c++) acc[r][c] = 0ull;

    const ulonglong2* Wv2 = (const ulonglong2*)Wp;  // [kp][64] of ulonglong2
#pragma unroll 4
    for (int kp = 0; kp < 64; kp++) {
        ulonglong2 wa = Wv2[kp * 64 + (j0 >> 1)];      // cols j0, j0+1
        ulonglong2 wb = Wv2[kp * 64 + (j0 >> 1) + 1];  // cols j0+2, j0+3
        ull x0 = mt_in[kp * 32 + eq];
        ull x1 = mt_in[kp * 32 + eq + 8];
        ull x2 = mt_in[kp * 32 + eq + 16];
        ull x3 = mt_in[kp * 32 + eq + 24];
        FMA2(acc[0][0], x0, wa.x, acc[0][0]); FMA2(acc[0][1], x0, wa.y, acc[0][1]);
        FMA2(acc[0][2], x0, wb.x, acc[0][2]); FMA2(acc[0][3], x0, wb.y, acc[0][3]);
        FMA2(acc[1][0], x1, wa.x, acc[1][0]); FMA2(acc[1][1], x1, wa.y, acc[1][1]);
        FMA2(acc[1][2], x1, wb.x, acc[1][2]); FMA2(acc[1][3], x1, wb.y, acc[1][3]);
        FMA2(acc[2][0], x2, wa.x, acc[2][0]); FMA2(acc[2][1], x2, wa.y, acc[2][1]);
        FMA2(acc[2][2], x2, wb.x, acc[2][2]); FMA2(acc[2][3], x2, wb.y, acc[2][3]);
        FMA2(acc[3][0], x3, wa.x, acc[3][0]); FMA2(acc[3][1], x3, wa.y, acc[3][1]);
        FMA2(acc[3][2], x3, wb.x, acc[3][2]); FMA2(acc[3][3], x3, wb.y, acc[3][3]);
    }

    float4 bb = *(const float4*)&bias[j0];
#pragma unroll
    for (int r = 0; r < 4; r++) {
        int e = eq + 8 * r;
        float4 o;
        o.x = silu_f(lo_f(acc[r][0]) + hi_f(acc[r][0]) + bb.x);
        o.y = silu_f(lo_f(acc[r][1]) + hi_f(acc[r][1]) + bb.y);
        o.z = silu_f(lo_f(acc[r][2]) + hi_f(acc[r][2]) + bb.z);
        o.w = silu_f(lo_f(acc[r][3]) + hi_f(acc[r][3]) + bb.w);
        mt_out[(j0 >> 1) * 32 + e]       = packf2(o.x, o.y);
        mt_out[((j0 >> 1) + 1) * 32 + e] = packf2(o.z, o.w);
        if (WRITE_ROWS)
            *(float4*)&rows_out[e * MS + j0] = o;
    }
}

__global__ __launch_bounds__(NTHR, 3)
void edge_kernel(const float* __restrict__ m_w1,
                 const float* __restrict__ m_b1,
                 const float* __restrict__ m_b2,
                 const float* __restrict__ c_b1) {
    extern __shared__ char smem_raw[];
    EdgeSmem& sm = *reinterpret_cast<EdgeSmem*>(smem_raw);

    const int tid = threadIdx.x;
    const long tileBase = (long)blockIdx.x * TILE_E;

    // stage W1c (radial rows) + b1
    for (int i = tid; i < 8 * 128; i += NTHR) sm.w1c[i] = m_w1[256 * 128 + i];
    if (tid < 128) sm.b1s[tid] = m_b1[tid];

    // load meta + rad
    if (tid < TILE_E) {
        long ge = tileBase + tid;
        int4 m = g_meta[ge];
        sm.s_tgt[tid] = m.x;
        sm.s_src[tid] = m.y;
        sm.s_ts[tid]  = m.z;
        sm.s_ew[tid]  = __int_as_float(m.w);
        sm.s_wr[tid]  = g_wr[ge];
    }
    if (tid < TILE_E * 8)
        sm.rad[tid] = g_rad[tileBase * 8 + tid];
    __syncthreads();

    // ---- m1 = silu(Ah[tgt] + Bh[src] + rad @ W1c + b1) -> mt1 [kp][e] ----
    {
        const int e = tid >> 3;          // 32 edges
        const int q = tid & 7;           // 8 col-quarters of 16
        const int j0 = q * 16;
        int t = sm.s_tgt[e];
        int s = sm.s_src[e];
        float r[8];
#pragma unroll
        for (int k = 0; k < 8; k++) r[k] = sm.rad[e * 8 + k];
#pragma unroll
        for (int v = 0; v < 4; v++) {
            int j = j0 + v * 4;
            float4 a  = *(const float4*)&g_Ah[(long)t * 128 + j];
            float4 b  = *(const float4*)&g_Bh[(long)s * 128 + j];
            float4 bb = *(const float4*)&sm.b1s[j];
            float4 acc;
            acc.x = a.x + b.x + bb.x;
            acc.y = a.y + b.y + bb.y;
            acc.z = a.z + b.z + bb.z;
            acc.w = a.w + b.w + bb.w;
#pragma unroll
            for (int k = 0; k < 8; k++) {
                float4 w = *(const float4*)&sm.w1c[k * 128 + j];
                acc.x = fmaf(r[k], w.x, acc.x);
                acc.y = fmaf(r[k], w.y, acc.y);
                acc.z = fmaf(r[k], w.z, acc.z);
                acc.w = fmaf(r[k], w.w, acc.w);
            }
            float ox = silu_f(acc.x), oy = silu_f(acc.y);
            float oz = silu_f(acc.z), ow = silu_f(acc.w);
            int jp = j >> 1;
            sm.mt1[jp * 32 + e]       = packf2(ox, oy);
            sm.mt1[(jp + 1) * 32 + e] = packf2(oz, ow);
        }
    }
    __syncthreads();

    // ---- GEMM chain (K-pair-major, 4 edges x 4 cols per thread) ----
    tile_gemm_t<true >(sm.mt1, g_W2p,  m_b2, sm.mt2, sm.ms2, tid);  // m
    __syncthreads();
    tile_gemm_t<false>(sm.mt2, g_CW1p, c_b1, sm.mt1, nullptr, tid); // cf
    __syncthreads();

    // edge_feat = cf @ c_w2  (32 edges x 8) from mt1
    {
        int e = tid >> 3;
        int j = tid & 7;
        ull acc = 0ull;
#pragma unroll 8
        for (int kp = 0; kp < 64; kp++) {
            ull cf = sm.mt1[kp * 32 + e];
            FMA2(acc, cf, g_CW2p[kp * 8 + j], acc);
        }
        sm.ef[e * 8 + j] = lo_f(acc) + hi_f(acc);
    }
    __syncthreads();

    // ---- aggregation atomics ----
    // node_agg[tgt] += m * ew   (row-format ms2, coalesced)
    for (int idx = tid; idx < TILE_E * 128; idx += NTHR) {
        int e = idx >> 7, j = idx & 127;
        int t = sm.s_tgt[e];
        atomicAdd(&g_node_agg[(long)t * 128 + j], sm.ms2[e * MS + j] * sm.s_ew[e]);
    }
    // coord_sum[tgt] += w_r * coord_diff * pooled_edge
    if (tid < TILE_E * 8) {
        int e = tid >> 3, a = tid & 7;
        int t = sm.s_tgt[e];
        int ts = sm.s_ts[e];
        int w = 8 - ts;
        int hi = a + w; if (hi > 8) hi = 8;
        float s = 0.f;
        for (int b = a; b < hi; b++) s += sm.ef[e * 8 + b];
        float pe = (s / (float)w) * sm.s_wr[e];
        long ge = tileBase + e;
#pragma unroll
        for (int k = 0; k < 3; k++)
            atomicAdd(&g_coord_sum[(long)t * 24 + a * 3 + k],
                      g_cdiff[ge * 24 + a * 3 + k] * pe);
    }
    // cnt[tgt] += 1
    if (tid < TILE_E) {
        atomicAdd(&g_cnt[sm.s_tgt[tid]], 1.f);
    }
}

// ---------------- node epilogue (R6 version) ----------------
__global__ __launch_bounds__(NTHR, 3)
void node_out_kernel(const float* __restrict__ h,
                     const float* __restrict__ coords,
                     const float* __restrict__ het_b,
                     const float* __restrict__ gamma,
                     const float* __restrict__ beta,
                     float* __restrict__ out) {
    __shared__ float ag[32 * MS];
    const int tid = threadIdx.x;
    const int base = blockIdx.x * 32;
    const float INVS = 0.9999950000374996f;  // 1/sqrt(1+1e-5)

    for (int idx = tid; idx < 32 * 128; idx += NTHR) {
        int n = idx >> 7, k = idx & 127;
        int gn = base + n;
        ag[n * MS + k] = (gn < NN) ? g_node_agg[(long)gn * 128 + k] : 0.f;
    }
    __syncthreads();

    const int cg = tid & 63;
    const int ng = tid >> 6;
    ull acc0[8], acc1[8];
#pragma unroll
    for (int r = 0; r < 8; r++) { acc0[r] = 0ull; acc1[r] = 0ull; }
    const ulonglong2* Wv = (const ulonglong2*)g_HWp;
#pragma unroll 4
    for (int kp = 0; kp < 64; kp++) {
        ulonglong2 w = Wv[kp * 64 + cg];
#pragma unroll
        for (int r = 0; r < 8; r++) {
            ull xv = *(const ull*)&ag[(ng * 8 + r) * MS + kp * 2];
            FMA2(acc0[r], xv, w.x, acc0[r]);
            FMA2(acc1[r], xv, w.y, acc1[r]);
        }
    }
    int j0 = cg * 2;
    float2 hb = *(const float2*)&het_b[j0];
    float2 gm = *(const float2*)&gamma[j0];
    float2 bt = *(const float2*)&beta[j0];
#pragma unroll
    for (int r = 0; r < 8; r++) {
        int gn = base + ng * 8 + r;
        if (gn < NN) {
            float2 o;
            o.x = silu_f((lo_f(acc0[r]) + hi_f(acc0[r]) + hb.x) * INVS * gm.x + bt.x);
            o.y = silu_f((lo_f(acc1[r]) + hi_f(acc1[r]) + hb.y) * INVS * gm.y + bt.y);
            float2 hv = *(const float2*)&h[(long)gn * 128 + j0];
            o.x += hv.x; o.y += hv.y;
            *(float2*)&out[(long)gn * 128 + j0] = o;
        }
    }

    for (int idx = tid; idx < 32 * 24; idx += NTHR) {
        int n = idx / 24, k = idx % 24;
        int gn = base + n;
        if (gn < NN) {
            float c = fmaxf(g_cnt[gn], 1.f);
            out[(long)NN * 128 + (long)gn * 24 + k] =
                coords[(long)gn * 24 + k] + g_coord_sum[(long)gn * 24 + k] / c;
        }
    }
}

// ---------------- launch ----------------
extern "C" void kernel_launch(void* const* d_in, const int* in_sizes, int n_in,
                              void* d_out, int out_size) {
    (void)in_sizes; (void)n_in; (void)out_size;
    const float* h      = (const float*)d_in[0];
    const float* coords = (const float*)d_in[1];
    const float* ca     = (const float*)d_in[2];
    const float* cw     = (const float*)d_in[3];
    const float* ew     = (const float*)d_in[4];
    const int*   el     = (const int*)d_in[5];
    const float* rl_w   = (const float*)d_in[6];
    const float* rl_b   = (const float*)d_in[7];
    const float* m_w1   = (const float*)d_in[8];
    const float* m_b1   = (const float*)d_in[9];
    const float* m_w2   = (const float*)d_in[10];
    const float* m_b2   = (const float*)d_in[11];
    const float* c_w1   = (const float*)d_in[12];
    const float* c_b1   = (const float*)d_in[13];
    const float* c_w2   = (const float*)d_in[14];
    const float* het_w  = (const float*)d_in[15];
    const float* het_b  = (const float*)d_in[16];
    const float* gamma  = (const float*)d_in[17];
    const float* beta   = (const float*)d_in[18];
    const float* w_r    = (const float*)d_in[19];
    float* out = (float*)d_out;

    cudaFuncSetAttribute(edge_kernel, cudaFuncAttributeMaxDynamicSharedMemorySize,
                         (int)sizeof(EdgeSmem));

    zero_kernel<<<2048, 256>>>();
    pack_kernel<<<132, 256>>>(m_w1, m_w2, c_w1, c_w2, het_w);
    node_pre_kernel<<<(NN + 255) / 256, 256>>>(coords, cw);
    node_gemm_kernel<<<(NN + 31) / 32, NTHR>>>(h);
    max_kernel<<<(EE + 255) / 256, 256>>>(coords, el);
    edge_pre_kernel<<<(EE + 7) / 8, 256>>>(coords, ca, cw, ew, el, rl_w, rl_b, w_r);
    edge_kernel<<<EE / TILE_E, NTHR, sizeof(EdgeSmem)>>>(m_w1, m_b1, m_b2, c_b1);
    node_out_kernel<<<(NN + 31) / 32, NTHR>>>(h, coords, het_b, gamma, beta, out);
}

// round 11
// speedup vs baseline: 1.7469x; 1.2021x over previous
#include <cuda_runtime.h>
#include <mma.h>
#include <math.h>

using namespace nvcuda;

#define NN 50000
#define EE 400000
#define DD 128
#define CC 8

#define TILE_E 32
#define NTHR 256
#define MS 132   // row stride in floats (132*4 = 528 B, 16B-aligned rows)

typedef unsigned long long ull;

// ---------------- device scratch (no allocations allowed) ----------------
__device__ float g_node_agg[NN * DD];
__device__ float g_coord_sum[NN * CC * 3];
__device__ float g_cnt[NN];
__device__ float g_pcol[NN * 3];
__device__ int   g_csum[NN];
__device__ unsigned int g_maxbits;
__device__ float g_Ah[NN * DD];
__device__ float g_Bh[NN * DD];

// edge-pre outputs
__device__ float g_rad[EE * 8];
__device__ float g_cdiff[EE * 24];
__device__ int4  g_meta[EE];
__device__ float g_wr[EE];

// K-pair-interleaved packed weights (still used by FFMA2 kernels)
__device__ ull g_W1p[128 * 128];   // m_w1 rows 0..255
__device__ ull g_HWp[64 * 128];    // het_w
__device__ ull g_CW2p[64 * 8];     // c_w2

__device__ __forceinline__ float silu_f(float x) {
    return x * (1.0f / (1.0f + __expf(-x)));
}
__device__ __forceinline__ ull packf2(float lo, float hi) {
    return ((ull)__float_as_uint(hi) << 32) | (ull)__float_as_uint(lo);
}
__device__ __forceinline__ float lo_f(ull p) { return __uint_as_float((unsigned)(p & 0xffffffffull)); }
__device__ __forceinline__ float hi_f(ull p) { return __uint_as_float((unsigned)(p >> 32)); }

#define FMA2(d, a, b, c) asm("fma.rn.f32x2 %0, %1, %2, %3;" : "=l"(d) : "l"(a), "l"(b), "l"(c))

// ---------------- zero scratch ----------------
__global__ void zero_kernel() {
    long t0 = (long)blockIdx.x * blockDim.x + threadIdx.x;
    long stride = (long)gridDim.x * blockDim.x;
    for (long i = t0; i < (long)NN * DD; i += stride) g_node_agg[i] = 0.f;
    for (long i = t0; i < (long)NN * 24; i += stride) g_coord_sum[i] = 0.f;
    for (long i = t0; i < NN; i += stride) g_cnt[i] = 0.f;
    if (t0 == 0) g_maxbits = 0u;
}

// ---------------- weight pre-packing ----------------
__global__ void pack_kernel(const float* __restrict__ m_w1,
                            const float* __restrict__ c_w2,
                            const float* __restrict__ het_w) {
    int t0 = blockIdx.x * blockDim.x + threadIdx.x;
    int stride = gridDim.x * blockDim.x;
    for (int i = t0; i < 128 * 128; i += stride) {
        int kp = i >> 7, j = i & 127;
        g_W1p[i] = packf2(m_w1[(2 * kp) * 128 + j], m_w1[(2 * kp + 1) * 128 + j]);
    }
    for (int i = t0; i < 64 * 128; i += stride) {
        int kp = i >> 7, j = i & 127;
        g_HWp[i] = packf2(het_w[(2 * kp) * 128 + j], het_w[(2 * kp + 1) * 128 + j]);
    }
    for (int i = t0; i < 64 * 8; i += stride) {
        int kp = i >> 3, j = i & 7;
        g_CW2p[i] = packf2(c_w2[(2 * kp) * 8 + j], c_w2[(2 * kp + 1) * 8 + j]);
    }
}

// ---------------- per-node precompute: csum, pooled_col ----------------
__global__ void node_pre_kernel(const float* __restrict__ coords,
                                const float* __restrict__ cw) {
    int n = blockIdx.x * blockDim.x + threadIdx.x;
    if (n >= NN) return;
    float px = 0.f, py = 0.f, pz = 0.f;
    int cs = 0;
#pragma unroll
    for (int c = 0; c < 8; c++) {
        float w = cw[n * 8 + c];
        if (w != 0.f) {
            cs++;
            px += coords[n * 24 + c * 3 + 0];
            py += coords[n * 24 + c * 3 + 1];
            pz += coords[n * 24 + c * 3 + 2];
        }
    }
    float inv = 1.f / ((float)cs + 0.001f);
    g_pcol[n * 3 + 0] = px * inv;
    g_pcol[n * 3 + 1] = py * inv;
    g_pcol[n * 3 + 2] = pz * inv;
    g_csum[n] = cs;
}

// ---------------- global max of squared channel distances ----------------
__global__ void max_kernel(const float* __restrict__ coords,
                           const int* __restrict__ el) {
    int e = blockIdx.x * blockDim.x + threadIdx.x;
    float m = 0.f;
    if (e < EE) {
        int src = el[e * 3 + 0];
        int tgt = el[e * 3 + 1];
        float ct[24], cs[24];
#pragma unroll
        for (int i = 0; i < 24; i++) {
            ct[i] = coords[(long)tgt * 24 + i];
            cs[i] = coords[(long)src * 24 + i];
        }
#pragma unroll
        for (int c = 0; c < 8; c++) {
#pragma unroll
            for (int d = 0; d < 8; d++) {
                float dx = ct[c * 3 + 0] - cs[d * 3 + 0];
                float dy = ct[c * 3 + 1] - cs[d * 3 + 1];
                float dz = ct[c * 3 + 2] - cs[d * 3 + 2];
                float ns = dx * dx + dy * dy + dz * dz;
                m = fmaxf(m, ns);
            }
        }
    }
#pragma unroll
    for (int o = 16; o > 0; o >>= 1)
        m = fmaxf(m, __shfl_xor_sync(0xffffffffu, m, o));
    if ((threadIdx.x & 31) == 0)
        atomicMax(&g_maxbits, __float_as_uint(m));
}

// ---------------- per-node GEMM: Ah = h@W1a, Bh = h@W1b  (R6 version) ----------------
__global__ __launch_bounds__(NTHR, 3)
void node_gemm_kernel(const float* __restrict__ h) {
    __shared__ float hs[32 * MS];
    const int tid = threadIdx.x;
    const int base = blockIdx.x * 32;

    for (int idx = tid; idx < 32 * 128; idx += NTHR) {
        int n = idx >> 7, k = idx & 127;
        int gn = base + n;
        hs[n * MS + k] = (gn < NN) ? h[(long)gn * 128 + k] : 0.f;
    }
    __syncthreads();

    const int cg = tid & 63;
    const int ng = tid >> 6;
#pragma unroll
    for (int half = 0; half < 2; half++) {
        float* dst = half ? g_Bh : g_Ah;
        const ulonglong2* Wv = (const ulonglong2*)(g_W1p + half * 64 * 128);
        ull acc0[8], acc1[8];
#pragma unroll
        for (int r = 0; r < 8; r++) { acc0[r] = 0ull; acc1[r] = 0ull; }
#pragma unroll 4
        for (int kp = 0; kp < 64; kp++) {
            ulonglong2 w = Wv[kp * 64 + cg];
#pragma unroll
            for (int r = 0; r < 8; r++) {
                ull xv = *(const ull*)&hs[(ng * 8 + r) * MS + kp * 2];
                FMA2(acc0[r], xv, w.x, acc0[r]);
                FMA2(acc1[r], xv, w.y, acc1[r]);
            }
        }
#pragma unroll
        for (int r = 0; r < 8; r++) {
            int gn = base + ng * 8 + r;
            if (gn < NN) {
                float2 o;
                o.x = lo_f(acc0[r]) + hi_f(acc0[r]);
                o.y = lo_f(acc1[r]) + hi_f(acc1[r]);
                *(float2*)&dst[(long)gn * 128 + cg * 2] = o;
            }
        }
    }
}

// ---------------- edge preprocessing: one edge per warp (R6 version) ----------------
__global__ __launch_bounds__(256)
void edge_pre_kernel(const float* __restrict__ coords,
                     const float* __restrict__ ca,
                     const float* __restrict__ cw,
                     const float* __restrict__ edge_weights,
                     const int* __restrict__ el,
                     const float* __restrict__ rl_w,
                     const float* __restrict__ rl_b,
                     const float* __restrict__ w_r) {
    __shared__ float wscr[8][320];
    const int wid = threadIdx.x >> 5;
    const int lane = threadIdx.x & 31;
    const long ge = (long)blockIdx.x * 8 + wid;
    if (ge >= (long)EE) return;

    float gmax = sqrtf(__uint_as_float(g_maxbits));
    float inv_g = 1.f / (gmax + 0.001f);

    float* WS  = &wscr[wid][0];
    float* At  = WS;
    float* Bs  = WS + 64;
    float* Mm  = WS + 128;
    float* Tt  = WS + 192;
    float* cwt = WS + 256;
    float* cws = WS + 264;
    float* ctb = WS + 272;
    float* csb = WS + 296;

    int src = el[ge * 3 + 0];
    int tgt = el[ge * 3 + 1];
    int rel = el[ge * 3 + 2];

    At[lane]      = ca[(long)tgt * 64 + lane];
    At[lane + 32] = ca[(long)tgt * 64 + lane + 32];
    Bs[lane]      = ca[(long)src * 64 + lane];
    Bs[lane + 32] = ca[(long)src * 64 + lane + 32];
    if (lane < 8) { cwt[lane] = cw[(long)tgt * 8 + lane]; cws[lane] = cw[(long)src * 8 + lane]; }
    if (lane < 24) { ctb[lane] = coords[(long)tgt * 24 + lane]; csb[lane] = coords[(long)src * 24 + lane]; }
    __syncwarp();

#pragma unroll
    for (int half = 0; half < 2; half++) {
        int idx = lane + half * 32;
        int c = idx >> 3, d = idx & 7;
        float dx = ctb[c * 3 + 0] - csb[d * 3 + 0];
        float dy = ctb[c * 3 + 1] - csb[d * 3 + 1];
        float dz = ctb[c * 3 + 2] - csb[d * 3 + 2];
        float ns = dx * dx + dy * dy + dz * dz;
        float nrm = (ns > 0.f) ? ns * rsqrtf(ns) : 0.f;
        Mm[idx] = nrm * inv_g * cwt[c] * cws[d];
    }
    __syncwarp();

#pragma unroll
    for (int half = 0; half < 2; half++) {
        int idx = lane + half * 32;
        int a = idx >> 3, d = idx & 7;
        float t = 0.f;
#pragma unroll
        for (int c = 0; c < 8; c++) t = fmaf(At[c * 8 + a], Mm[c * 8 + d], t);
        Tt[idx] = t;
    }
    __syncwarp();

    float r0 = 0.f, r1 = 0.f;
    {
        int a = lane >> 3, b = lane & 7;
#pragma unroll
        for (int d = 0; d < 8; d++) r0 = fmaf(Tt[a * 8 + d], Bs[d * 8 + b], r0);
        int idx = lane + 32;
        a = idx >> 3; b = idx & 7;
#pragma unroll
        for (int d = 0; d < 8; d++) r1 = fmaf(Tt[a * 8 + d], Bs[d * 8 + b], r1);
    }
    float ss = r0 * r0 + r1 * r1;
#pragma unroll
    for (int o = 16; o > 0; o >>= 1) ss += __shfl_xor_sync(0xffffffffu, ss, o);
    float invn = 1.f / (sqrtf(ss) + 0.001f);
    Mm[lane] = r0;
    Mm[lane + 32] = r1;
    __syncwarp();

    if (lane < 8) {
        float acc = 0.f;
#pragma unroll
        for (int k = 0; k < 64; k++) acc = fmaf(Mm[k], rl_w[k * 8 + lane], acc);
        g_rad[ge * 8 + lane] = acc * invn + rl_b[lane];
    }
    if (lane < 24) {
        int k = lane % 3;
        g_cdiff[ge * 24 + lane] = ctb[lane] - g_pcol[(long)src * 3 + k];
    }
    if (lane == 0) {
        int cs = g_csum[tgt];
        int ts = cs - 1;
        ts = ts < 0 ? 0 : (ts > 7 ? 7 : ts);
        g_meta[ge] = make_int4(tgt, src, ts, __float_as_int(edge_weights[ge]));
        g_wr[ge] = w_r[rel];
    }
}

// ---------------- fused edge GEMM kernel: wmma tf32 for GEMM2/GEMM3 ----------------
struct __align__(128) EdgeSmem {
    float ms1[TILE_E * MS];    // m1 (silu'd) / later cf
    float ms2[TILE_E * MS];    // m
    float w1c[8 * 128];        // m_w1 rows 256..263 (radial part)
    float b1s[128];
    float b2s[128];            // m_b2
    float cb1s[128];           // c_b1
    float rad[TILE_E * 8];
    float ef[TILE_E * 8];
    int   s_tgt[TILE_E];
    int   s_src[TILE_E];
    float s_ew[TILE_E];
    float s_wr[TILE_E];
    int   s_ts[TILE_E];
};

// wmma tf32 GEMM: dst(32x128, stride MS) = src(32x128, stride MS) @ W(128x128 row-major, global)
// 8 warps: warp w -> m-tile (w&1), n-tiles {2*(w>>1), 2*(w>>1)+1}
__device__ __forceinline__ void wmma_gemm_32x128x128(const float* __restrict__ src,
                                                     const float* __restrict__ W,
                                                     float* __restrict__ dst,
                                                     int tid) {
    const int w   = tid >> 5;
    const int mt  = w & 1;
    const int nt0 = (w >> 1) * 2;

    wmma::fragment<wmma::accumulator, 16, 16, 8, float> c0, c1;
    wmma::fill_fragment(c0, 0.f);
    wmma::fill_fragment(c1, 0.f);

    for (int k = 0; k < 16; k++) {
        wmma::fragment<wmma::matrix_a, 16, 16, 8, wmma::precision::tf32, wmma::row_major> fa;
        wmma::fragment<wmma::matrix_b, 16, 16, 8, wmma::precision::tf32, wmma::row_major> fb0, fb1;
        wmma::load_matrix_sync(fa, src + (mt * 16) * MS + k * 8, MS);
#pragma unroll
        for (int i = 0; i < fa.num_elements; i++) fa.x[i] = wmma::__float_to_tf32(fa.x[i]);
        wmma::load_matrix_sync(fb0, W + (k * 8) * 128 + nt0 * 16, 128);
        wmma::load_matrix_sync(fb1, W + (k * 8) * 128 + (nt0 + 1) * 16, 128);
#pragma unroll
        for (int i = 0; i < fb0.num_elements; i++) fb0.x[i] = wmma::__float_to_tf32(fb0.x[i]);
#pragma unroll
        for (int i = 0; i < fb1.num_elements; i++) fb1.x[i] = wmma::__float_to_tf32(fb1.x[i]);
        wmma::mma_sync(c0, fa, fb0, c0);
        wmma::mma_sync(c1, fa, fb1, c1);
    }
    wmma::store_matrix_sync(dst + (mt * 16) * MS + nt0 * 16, c0, MS, wmma::mem_row_major);
    wmma::store_matrix_sync(dst + (mt * 16) * MS + (nt0 + 1) * 16, c1, MS, wmma::mem_row_major);
}

// in-place bias + silu over 32x128 tile (stride MS)
__device__ __forceinline__ void bias_silu_pass(float* __restrict__ buf,
                                               const float* __restrict__ bias,
                                               int tid) {
    for (int idx = tid; idx < TILE_E * 32; idx += NTHR) {
        int e = idx >> 5, jq = idx & 31;
        int j = jq * 4;
        float4 v  = *(const float4*)&buf[e * MS + j];
        float4 bb = *(const float4*)&bias[j];
        v.x = silu_f(v.x + bb.x);
        v.y = silu_f(v.y + bb.y);
        v.z = silu_f(v.z + bb.z);
        v.w = silu_f(v.w + bb.w);
        *(float4*)&buf[e * MS + j] = v;
    }
}

__global__ __launch_bounds__(NTHR, 3)
void edge_kernel(const float* __restrict__ m_w1,
                 const float* __restrict__ m_b1,
                 const float* __restrict__ m_w2,
                 const float* __restrict__ m_b2,
                 const float* __restrict__ c_w1,
                 const float* __restrict__ c_b1) {
    extern __shared__ char smem_raw[];
    EdgeSmem& sm = *reinterpret_cast<EdgeSmem*>(smem_raw);

    const int tid = threadIdx.x;
    const long tileBase = (long)blockIdx.x * TILE_E;

    // stage W1c (radial rows) + biases
    for (int i = tid; i < 8 * 128; i += NTHR) sm.w1c[i] = m_w1[256 * 128 + i];
    if (tid < 128) {
        sm.b1s[tid]  = m_b1[tid];
        sm.b2s[tid]  = m_b2[tid];
        sm.cb1s[tid] = c_b1[tid];
    }

    // load meta + rad (coalesced)
    if (tid < TILE_E) {
        long ge = tileBase + tid;
        int4 m = g_meta[ge];
        sm.s_tgt[tid] = m.x;
        sm.s_src[tid] = m.y;
        sm.s_ts[tid]  = m.z;
        sm.s_ew[tid]  = __int_as_float(m.w);
        sm.s_wr[tid]  = g_wr[ge];
    }
    if (tid < TILE_E * 8)
        sm.rad[tid] = g_rad[tileBase * 8 + tid];
    __syncthreads();

    // ---- m1 = silu(Ah[tgt] + Bh[src] + rad @ W1c + b1) -> ms1 ----
    {
        const int e = tid >> 3;          // 32 edges
        const int q = tid & 7;           // 8 col-quarters of 16
        const int j0 = q * 16;
        int t = sm.s_tgt[e];
        int s = sm.s_src[e];
        float r[8];
#pragma unroll
        for (int k = 0; k < 8; k++) r[k] = sm.rad[e * 8 + k];
#pragma unroll
        for (int v = 0; v < 4; v++) {
            int j = j0 + v * 4;
            float4 a  = *(const float4*)&g_Ah[(long)t * 128 + j];
            float4 b  = *(const float4*)&g_Bh[(long)s * 128 + j];
            float4 bb = *(const float4*)&sm.b1s[j];
            float4 acc;
            acc.x = a.x + b.x + bb.x;
            acc.y = a.y + b.y + bb.y;
            acc.z = a.z + b.z + bb.z;
            acc.w = a.w + b.w + bb.w;
#pragma unroll
            for (int k = 0; k < 8; k++) {
                float4 w = *(const float4*)&sm.w1c[k * 128 + j];
                acc.x = fmaf(r[k], w.x, acc.x);
                acc.y = fmaf(r[k], w.y, acc.y);
                acc.z = fmaf(r[k], w.z, acc.z);
                acc.w = fmaf(r[k], w.w, acc.w);
            }
            float4 o;
            o.x = silu_f(acc.x); o.y = silu_f(acc.y);
            o.z = silu_f(acc.z); o.w = silu_f(acc.w);
            *(float4*)&sm.ms1[e * MS + j] = o;
        }
    }
    __syncthreads();

    // ---- GEMM2 via wmma tf32: ms2_raw = ms1 @ m_w2 ----
    wmma_gemm_32x128x128(sm.ms1, m_w2, sm.ms2, tid);
    __syncthreads();
    bias_silu_pass(sm.ms2, sm.b2s, tid);   // ms2 = m = silu(. + b2)
    __syncthreads();

    // ---- GEMM3 via wmma tf32: ms1_raw = ms2 @ c_w1 ----
    wmma_gemm_32x128x128(sm.ms2, c_w1, sm.ms1, tid);
    __syncthreads();
    bias_silu_pass(sm.ms1, sm.cb1s, tid);  // ms1 = cf = silu(. + cb1)
    __syncthreads();

    // ---- edge_feat = cf @ c_w2  (32 edges x 8), packed-K FFMA2 ----
    {
        int e = tid >> 3;
        int j = tid & 7;
        ull acc = 0ull;
#pragma unroll 8
        for (int kp = 0; kp < 64; kp++) {
            ull cf = *(const ull*)&sm.ms1[e * MS + kp * 2];
            FMA2(acc, cf, g_CW2p[kp * 8 + j], acc);
        }
        sm.ef[e * 8 + j] = lo_f(acc) + hi_f(acc);
    }
    __syncthreads();

    // ---- aggregation atomics ----
    for (int idx = tid; idx < TILE_E * 128; idx += NTHR) {
        int e = idx >> 7, j = idx & 127;
        int t = sm.s_tgt[e];
        atomicAdd(&g_node_agg[(long)t * 128 + j], sm.ms2[e * MS + j] * sm.s_ew[e]);
    }
    if (tid < TILE_E * 8) {
        int e = tid >> 3, a = tid & 7;
        int t = sm.s_tgt[e];
        int ts = sm.s_ts[e];
        int w = 8 - ts;
        int hi = a + w; if (hi > 8) hi = 8;
        float s = 0.f;
        for (int b = a; b < hi; b++) s += sm.ef[e * 8 + b];
        float pe = (s / (float)w) * sm.s_wr[e];
        long ge = tileBase + e;
#pragma unroll
        for (int k = 0; k < 3; k++)
            atomicAdd(&g_coord_sum[(long)t * 24 + a * 3 + k],
                      g_cdiff[ge * 24 + a * 3 + k] * pe);
    }
    if (tid < TILE_E) {
        atomicAdd(&g_cnt[sm.s_tgt[tid]], 1.f);
    }
}

// ---------------- node epilogue (R6 version) ----------------
__global__ __launch_bounds__(NTHR, 3)
void node_out_kernel(const float* __restrict__ h,
                     const float* __restrict__ coords,
                     const float* __restrict__ het_b,
                     const float* __restrict__ gamma,
                     const float* __restrict__ beta,
                     float* __restrict__ out) {
    __shared__ float ag[32 * MS];
    const int tid = threadIdx.x;
    const int base = blockIdx.x * 32;
    const float INVS = 0.9999950000374996f;  // 1/sqrt(1+1e-5)

    for (int idx = tid; idx < 32 * 128; idx += NTHR) {
        int n = idx >> 7, k = idx & 127;
        int gn = base + n;
        ag[n * MS + k] = (gn < NN) ? g_node_agg[(long)gn * 128 + k] : 0.f;
    }
    __syncthreads();

    const int cg = tid & 63;
    const int ng = tid >> 6;
    ull acc0[8], acc1[8];
#pragma unroll
    for (int r = 0; r < 8; r++) { acc0[r] = 0ull; acc1[r] = 0ull; }
    const ulonglong2* Wv = (const ulonglong2*)g_HWp;
#pragma unroll 4
    for (int kp = 0; kp < 64; kp++) {
        ulonglong2 w = Wv[kp * 64 + cg];
#pragma unroll
        for (int r = 0; r < 8; r++) {
            ull xv = *(const ull*)&ag[(ng * 8 + r) * MS + kp * 2];
            FMA2(acc0[r], xv, w.x, acc0[r]);
            FMA2(acc1[r], xv, w.y, acc1[r]);
        }
    }
    int j0 = cg * 2;
    float2 hb = *(const float2*)&het_b[j0];
    float2 gm = *(const float2*)&gamma[j0];
    float2 bt = *(const float2*)&beta[j0];
#pragma unroll
    for (int r = 0; r < 8; r++) {
        int gn = base + ng * 8 + r;
        if (gn < NN) {
            float2 o;
            o.x = silu_f((lo_f(acc0[r]) + hi_f(acc0[r]) + hb.x) * INVS * gm.x + bt.x);
            o.y = silu_f((lo_f(acc1[r]) + hi_f(acc1[r]) + hb.y) * INVS * gm.y + bt.y);
            float2 hv = *(const float2*)&h[(long)gn * 128 + j0];
            o.x += hv.x; o.y += hv.y;
            *(float2*)&out[(long)gn * 128 + j0] = o;
        }
    }

    for (int idx = tid; idx < 32 * 24; idx += NTHR) {
        int n = idx / 24, k = idx % 24;
        int gn = base + n;
        if (gn < NN) {
            float c = fmaxf(g_cnt[gn], 1.f);
            out[(long)NN * 128 + (long)gn * 24 + k] =
                coords[(long)gn * 24 + k] + g_coord_sum[(long)gn * 24 + k] / c;
        }
    }
}

// ---------------- launch ----------------
extern "C" void kernel_launch(void* const* d_in, const int* in_sizes, int n_in,
                              void* d_out, int out_size) {
    (void)in_sizes; (void)n_in; (void)out_size;
    const float* h      = (const float*)d_in[0];
    const float* coords = (const float*)d_in[1];
    const float* ca     = (const float*)d_in[2];
    const float* cw     = (const float*)d_in[3];
    const float* ew     = (const float*)d_in[4];
    const int*   el     = (const int*)d_in[5];
    const float* rl_w   = (const float*)d_in[6];
    const float* rl_b   = (const float*)d_in[7];
    const float* m_w1   = (const float*)d_in[8];
    const float* m_b1   = (const float*)d_in[9];
    const float* m_w2   = (const float*)d_in[10];
    const float* m_b2   = (const float*)d_in[11];
    const float* c_w1   = (const float*)d_in[12];
    const float* c_b1   = (const float*)d_in[13];
    const float* c_w2   = (const float*)d_in[14];
    const float* het_w  = (const float*)d_in[15];
    const float* het_b  = (const float*)d_in[16];
    const float* gamma  = (const float*)d_in[17];
    const float* beta   = (const float*)d_in[18];
    const float* w_r    = (const float*)d_in[19];
    float* out = (float*)d_out;

    cudaFuncSetAttribute(edge_kernel, cudaFuncAttributeMaxDynamicSharedMemorySize,
                         (int)sizeof(EdgeSmem));

    zero_kernel<<<2048, 256>>>();
    pack_kernel<<<132, 256>>>(m_w1, c_w2, het_w);
    node_pre_kernel<<<(NN + 255) / 256, 256>>>(coords, cw);
    node_gemm_kernel<<<(NN + 31) / 32, NTHR>>>(h);
    max_kernel<<<(EE + 255) / 256, 256>>>(coords, el);
    edge_pre_kernel<<<(EE + 7) / 8, 256>>>(coords, ca, cw, ew, el, rl_w, rl_b, w_r);
    edge_kernel<<<EE / TILE_E, NTHR, sizeof(EdgeSmem)>>>(
        m_w1, m_b1, m_w2, m_b2, c_w1, c_b1);
    node_out_kernel<<<(NN + 31) / 32, NTHR>>>(h, coords, het_b, gamma, beta, out);
}

// round 12
// speedup vs baseline: 1.7915x; 1.0256x over previous
#include <cuda_runtime.h>
#include <mma.h>
#include <math.h>

using namespace nvcuda;

#define NN 50000
#define EE 400000
#define DD 128
#define CC 8

#define TILE_E 32
#define NTHR 256
#define MS 132   // row stride in floats (132*4 = 528 B, 16B-aligned rows)

typedef unsigned long long ull;

// ---------------- device scratch (no allocations allowed) ----------------
__device__ float g_node_agg[NN * DD];
__device__ float g_coord_sum[NN * CC * 3];
__device__ float g_cnt[NN];
__device__ float g_pcol[NN * 3];
__device__ int   g_csum[NN];
__device__ unsigned int g_maxbits;
__device__ float g_Ah[(NN + 32) * DD];   // +32 rows padding for wmma tile overrun
__device__ float g_Bh[(NN + 32) * DD];

// edge-pre outputs
__device__ float g_rad[EE * 8];
__device__ float g_cdiff[EE * 24];
__device__ int4  g_meta[EE];
__device__ float g_wr[EE];

// packed weights for the small FFMA2 path
__device__ ull g_CW2p[64 * 8];     // c_w2

__device__ __forceinline__ float silu_f(float x) {
    return x * (1.0f / (1.0f + __expf(-x)));
}
__device__ __forceinline__ ull packf2(float lo, float hi) {
    return ((ull)__float_as_uint(hi) << 32) | (ull)__float_as_uint(lo);
}
__device__ __forceinline__ float lo_f(ull p) { return __uint_as_float((unsigned)(p & 0xffffffffull)); }
__device__ __forceinline__ float hi_f(ull p) { return __uint_as_float((unsigned)(p >> 32)); }

#define FMA2(d, a, b, c) asm("fma.rn.f32x2 %0, %1, %2, %3;" : "=l"(d) : "l"(a), "l"(b), "l"(c))

// ---------------- shared wmma helper ----------------
// dst(32x128, dst_stride) = src(32x128, stride MS) @ W(128x128 row-major)
// 8 warps: warp w -> m-tile (w&1), n-tiles {2*(w>>1), 2*(w>>1)+1}
__device__ __forceinline__ void wmma_gemm_32x128x128(const float* __restrict__ src,
                                                     const float* __restrict__ W,
                                                     float* __restrict__ dst,
                                                     int dst_stride,
                                                     int tid) {
    const int w   = tid >> 5;
    const int mt  = w & 1;
    const int nt0 = (w >> 1) * 2;

    wmma::fragment<wmma::accumulator, 16, 16, 8, float> c0, c1;
    wmma::fill_fragment(c0, 0.f);
    wmma::fill_fragment(c1, 0.f);

    for (int k = 0; k < 16; k++) {
        wmma::fragment<wmma::matrix_a, 16, 16, 8, wmma::precision::tf32, wmma::row_major> fa;
        wmma::fragment<wmma::matrix_b, 16, 16, 8, wmma::precision::tf32, wmma::row_major> fb0, fb1;
        wmma::load_matrix_sync(fa, src + (mt * 16) * MS + k * 8, MS);
#pragma unroll
        for (int i = 0; i < fa.num_elements; i++) fa.x[i] = wmma::__float_to_tf32(fa.x[i]);
        wmma::load_matrix_sync(fb0, W + (k * 8) * 128 + nt0 * 16, 128);
        wmma::load_matrix_sync(fb1, W + (k * 8) * 128 + (nt0 + 1) * 16, 128);
#pragma unroll
        for (int i = 0; i < fb0.num_elements; i++) fb0.x[i] = wmma::__float_to_tf32(fb0.x[i]);
#pragma unroll
        for (int i = 0; i < fb1.num_elements; i++) fb1.x[i] = wmma::__float_to_tf32(fb1.x[i]);
        wmma::mma_sync(c0, fa, fb0, c0);
        wmma::mma_sync(c1, fa, fb1, c1);
    }
    wmma::store_matrix_sync(dst + (mt * 16) * dst_stride + nt0 * 16, c0, dst_stride, wmma::mem_row_major);
    wmma::store_matrix_sync(dst + (mt * 16) * dst_stride + (nt0 + 1) * 16, c1, dst_stride, wmma::mem_row_major);
}

// ---------------- zero scratch ----------------
__global__ void zero_kernel() {
    long t0 = (long)blockIdx.x * blockDim.x + threadIdx.x;
    long stride = (long)gridDim.x * blockDim.x;
    for (long i = t0; i < (long)NN * DD; i += stride) g_node_agg[i] = 0.f;
    for (long i = t0; i < (long)NN * 24; i += stride) g_coord_sum[i] = 0.f;
    for (long i = t0; i < NN; i += stride) g_cnt[i] = 0.f;
    if (t0 == 0) g_maxbits = 0u;
}

// ---------------- weight pre-packing (c_w2 only) ----------------
__global__ void pack_kernel(const float* __restrict__ c_w2) {
    int t0 = blockIdx.x * blockDim.x + threadIdx.x;
    int stride = gridDim.x * blockDim.x;
    for (int i = t0; i < 64 * 8; i += stride) {
        int kp = i >> 3, j = i & 7;
        g_CW2p[i] = packf2(c_w2[(2 * kp) * 8 + j], c_w2[(2 * kp + 1) * 8 + j]);
    }
}

// ---------------- per-node precompute: csum, pooled_col ----------------
__global__ void node_pre_kernel(const float* __restrict__ coords,
                                const float* __restrict__ cw) {
    int n = blockIdx.x * blockDim.x + threadIdx.x;
    if (n >= NN) return;
    float px = 0.f, py = 0.f, pz = 0.f;
    int cs = 0;
#pragma unroll
    for (int c = 0; c < 8; c++) {
        float w = cw[n * 8 + c];
        if (w != 0.f) {
            cs++;
            px += coords[n * 24 + c * 3 + 0];
            py += coords[n * 24 + c * 3 + 1];
            pz += coords[n * 24 + c * 3 + 2];
        }
    }
    float inv = 1.f / ((float)cs + 0.001f);
    g_pcol[n * 3 + 0] = px * inv;
    g_pcol[n * 3 + 1] = py * inv;
    g_pcol[n * 3 + 2] = pz * inv;
    g_csum[n] = cs;
}

// ---------------- global max of squared channel distances ----------------
__global__ void max_kernel(const float* __restrict__ coords,
                           const int* __restrict__ el) {
    int e = blockIdx.x * blockDim.x + threadIdx.x;
    float m = 0.f;
    if (e < EE) {
        int src = el[e * 3 + 0];
        int tgt = el[e * 3 + 1];
        float ct[24], cs[24];
#pragma unroll
        for (int i = 0; i < 24; i++) {
            ct[i] = coords[(long)tgt * 24 + i];
            cs[i] = coords[(long)src * 24 + i];
        }
#pragma unroll
        for (int c = 0; c < 8; c++) {
#pragma unroll
            for (int d = 0; d < 8; d++) {
                float dx = ct[c * 3 + 0] - cs[d * 3 + 0];
                float dy = ct[c * 3 + 1] - cs[d * 3 + 1];
                float dz = ct[c * 3 + 2] - cs[d * 3 + 2];
                float ns = dx * dx + dy * dy + dz * dz;
                m = fmaxf(m, ns);
            }
        }
    }
#pragma unroll
    for (int o = 16; o > 0; o >>= 1)
        m = fmaxf(m, __shfl_xor_sync(0xffffffffu, m, o));
    if ((threadIdx.x & 31) == 0)
        atomicMax(&g_maxbits, __float_as_uint(m));
}

// ---------------- per-node GEMM via wmma tf32: Ah = h@W1a, Bh = h@W1b ----------------
__global__ __launch_bounds__(NTHR, 3)
void node_gemm_kernel(const float* __restrict__ h,
                      const float* __restrict__ m_w1) {
    __shared__ __align__(16) float hs[32 * MS];
    const int tid = threadIdx.x;
    const int base = blockIdx.x * 32;

    for (int idx = tid; idx < 32 * 128; idx += NTHR) {
        int n = idx >> 7, k = idx & 127;
        int gn = base + n;
        hs[n * MS + k] = (gn < NN) ? h[(long)gn * 128 + k] : 0.f;
    }
    __syncthreads();

    // Ah = hs @ m_w1[0:128], Bh = hs @ m_w1[128:256]; direct global store (padded)
    wmma_gemm_32x128x128(hs, m_w1,             &g_Ah[(long)base * 128], 128, tid);
    wmma_gemm_32x128x128(hs, m_w1 + 128 * 128, &g_Bh[(long)base * 128], 128, tid);
}

// ---------------- edge preprocessing: one edge per warp (R6 version) ----------------
__global__ __launch_bounds__(256)
void edge_pre_kernel(const float* __restrict__ coords,
                     const float* __restrict__ ca,
                     const float* __restrict__ cw,
                     const float* __restrict__ edge_weights,
                     const int* __restrict__ el,
                     const float* __restrict__ rl_w,
                     const float* __restrict__ rl_b,
                     const float* __restrict__ w_r) {
    __shared__ float wscr[8][320];
    const int wid = threadIdx.x >> 5;
    const int lane = threadIdx.x & 31;
    const long ge = (long)blockIdx.x * 8 + wid;
    if (ge >= (long)EE) return;

    float gmax = sqrtf(__uint_as_float(g_maxbits));
    float inv_g = 1.f / (gmax + 0.001f);

    float* WS  = &wscr[wid][0];
    float* At  = WS;
    float* Bs  = WS + 64;
    float* Mm  = WS + 128;
    float* Tt  = WS + 192;
    float* cwt = WS + 256;
    float* cws = WS + 264;
    float* ctb = WS + 272;
    float* csb = WS + 296;

    int src = el[ge * 3 + 0];
    int tgt = el[ge * 3 + 1];
    int rel = el[ge * 3 + 2];

    At[lane]      = ca[(long)tgt * 64 + lane];
    At[lane + 32] = ca[(long)tgt * 64 + lane + 32];
    Bs[lane]      = ca[(long)src * 64 + lane];
    Bs[lane + 32] = ca[(long)src * 64 + lane + 32];
    if (lane < 8) { cwt[lane] = cw[(long)tgt * 8 + lane]; cws[lane] = cw[(long)src * 8 + lane]; }
    if (lane < 24) { ctb[lane] = coords[(long)tgt * 24 + lane]; csb[lane] = coords[(long)src * 24 + lane]; }
    __syncwarp();

#pragma unroll
    for (int half = 0; half < 2; half++) {
        int idx = lane + half * 32;
        int c = idx >> 3, d = idx & 7;
        float dx = ctb[c * 3 + 0] - csb[d * 3 + 0];
        float dy = ctb[c * 3 + 1] - csb[d * 3 + 1];
        float dz = ctb[c * 3 + 2] - csb[d * 3 + 2];
        float ns = dx * dx + dy * dy + dz * dz;
        float nrm = (ns > 0.f) ? ns * rsqrtf(ns) : 0.f;
        Mm[idx] = nrm * inv_g * cwt[c] * cws[d];
    }
    __syncwarp();

#pragma unroll
    for (int half = 0; half < 2; half++) {
        int idx = lane + half * 32;
        int a = idx >> 3, d = idx & 7;
        float t = 0.f;
#pragma unroll
        for (int c = 0; c < 8; c++) t = fmaf(At[c * 8 + a], Mm[c * 8 + d], t);
        Tt[idx] = t;
    }
    __syncwarp();

    float r0 = 0.f, r1 = 0.f;
    {
        int a = lane >> 3, b = lane & 7;
#pragma unroll
        for (int d = 0; d < 8; d++) r0 = fmaf(Tt[a * 8 + d], Bs[d * 8 + b], r0);
        int idx = lane + 32;
        a = idx >> 3; b = idx & 7;
#pragma unroll
        for (int d = 0; d < 8; d++) r1 = fmaf(Tt[a * 8 + d], Bs[d * 8 + b], r1);
    }
    float ss = r0 * r0 + r1 * r1;
#pragma unroll
    for (int o = 16; o > 0; o >>= 1) ss += __shfl_xor_sync(0xffffffffu, ss, o);
    float invn = 1.f / (sqrtf(ss) + 0.001f);
    Mm[lane] = r0;
    Mm[lane + 32] = r1;
    __syncwarp();

    if (lane < 8) {
        float acc = 0.f;
#pragma unroll
        for (int k = 0; k < 64; k++) acc = fmaf(Mm[k], rl_w[k * 8 + lane], acc);
        g_rad[ge * 8 + lane] = acc * invn + rl_b[lane];
    }
    if (lane < 24) {
        int k = lane % 3;
        g_cdiff[ge * 24 + lane] = ctb[lane] - g_pcol[(long)src * 3 + k];
    }
    if (lane == 0) {
        int cs = g_csum[tgt];
        int ts = cs - 1;
        ts = ts < 0 ? 0 : (ts > 7 ? 7 : ts);
        g_meta[ge] = make_int4(tgt, src, ts, __float_as_int(edge_weights[ge]));
        g_wr[ge] = w_r[rel];
    }
}

// ---------------- fused edge GEMM kernel: wmma tf32 for GEMM2/GEMM3 (R11) ----------------
struct __align__(128) EdgeSmem {
    float ms1[TILE_E * MS];    // m1 (silu'd) / later cf
    float ms2[TILE_E * MS];    // m
    float w1c[8 * 128];        // m_w1 rows 256..263 (radial part)
    float b1s[128];
    float b2s[128];            // m_b2
    float cb1s[128];           // c_b1
    float rad[TILE_E * 8];
    float ef[TILE_E * 8];
    int   s_tgt[TILE_E];
    int   s_src[TILE_E];
    float s_ew[TILE_E];
    float s_wr[TILE_E];
    int   s_ts[TILE_E];
};

// in-place bias + silu over 32x128 tile (stride MS)
__device__ __forceinline__ void bias_silu_pass(float* __restrict__ buf,
                                               const float* __restrict__ bias,
                                               int tid) {
    for (int idx = tid; idx < TILE_E * 32; idx += NTHR) {
        int e = idx >> 5, jq = idx & 31;
        int j = jq * 4;
        float4 v  = *(const float4*)&buf[e * MS + j];
        float4 bb = *(const float4*)&bias[j];
        v.x = silu_f(v.x + bb.x);
        v.y = silu_f(v.y + bb.y);
        v.z = silu_f(v.z + bb.z);
        v.w = silu_f(v.w + bb.w);
        *(float4*)&buf[e * MS + j] = v;
    }
}

__global__ __launch_bounds__(NTHR, 3)
void edge_kernel(const float* __restrict__ m_w1,
                 const float* __restrict__ m_b1,
                 const float* __restrict__ m_w2,
                 const float* __restrict__ m_b2,
                 const float* __restrict__ c_w1,
                 const float* __restrict__ c_b1) {
    extern __shared__ char smem_raw[];
    EdgeSmem& sm = *reinterpret_cast<EdgeSmem*>(smem_raw);

    const int tid = threadIdx.x;
    const long tileBase = (long)blockIdx.x * TILE_E;

    // stage W1c (radial rows) + biases
    for (int i = tid; i < 8 * 128; i += NTHR) sm.w1c[i] = m_w1[256 * 128 + i];
    if (tid < 128) {
        sm.b1s[tid]  = m_b1[tid];
        sm.b2s[tid]  = m_b2[tid];
        sm.cb1s[tid] = c_b1[tid];
    }

    // load meta + rad (coalesced)
    if (tid < TILE_E) {
        long ge = tileBase + tid;
        int4 m = g_meta[ge];
        sm.s_tgt[tid] = m.x;
        sm.s_src[tid] = m.y;
        sm.s_ts[tid]  = m.z;
        sm.s_ew[tid]  = __int_as_float(m.w);
        sm.s_wr[tid]  = g_wr[ge];
    }
    if (tid < TILE_E * 8)
        sm.rad[tid] = g_rad[tileBase * 8 + tid];
    __syncthreads();

    // ---- m1 = silu(Ah[tgt] + Bh[src] + rad @ W1c + b1) -> ms1 ----
    {
        const int e = tid >> 3;          // 32 edges
        const int q = tid & 7;           // 8 col-quarters of 16
        const int j0 = q * 16;
        int t = sm.s_tgt[e];
        int s = sm.s_src[e];
        float r[8];
#pragma unroll
        for (int k = 0; k < 8; k++) r[k] = sm.rad[e * 8 + k];
#pragma unroll
        for (int v = 0; v < 4; v++) {
            int j = j0 + v * 4;
            float4 a  = *(const float4*)&g_Ah[(long)t * 128 + j];
            float4 b  = *(const float4*)&g_Bh[(long)s * 128 + j];
            float4 bb = *(const float4*)&sm.b1s[j];
            float4 acc;
            acc.x = a.x + b.x + bb.x;
            acc.y = a.y + b.y + bb.y;
            acc.z = a.z + b.z + bb.z;
            acc.w = a.w + b.w + bb.w;
#pragma unroll
            for (int k = 0; k < 8; k++) {
                float4 w = *(const float4*)&sm.w1c[k * 128 + j];
                acc.x = fmaf(r[k], w.x, acc.x);
                acc.y = fmaf(r[k], w.y, acc.y);
                acc.z = fmaf(r[k], w.z, acc.z);
                acc.w = fmaf(r[k], w.w, acc.w);
            }
            float4 o;
            o.x = silu_f(acc.x); o.y = silu_f(acc.y);
            o.z = silu_f(acc.z); o.w = silu_f(acc.w);
            *(float4*)&sm.ms1[e * MS + j] = o;
        }
    }
    __syncthreads();

    // ---- GEMM2 via wmma tf32: ms2_raw = ms1 @ m_w2 ----
    wmma_gemm_32x128x128(sm.ms1, m_w2, sm.ms2, MS, tid);
    __syncthreads();
    bias_silu_pass(sm.ms2, sm.b2s, tid);   // ms2 = m = silu(. + b2)
    __syncthreads();

    // ---- GEMM3 via wmma tf32: ms1_raw = ms2 @ c_w1 ----
    wmma_gemm_32x128x128(sm.ms2, c_w1, sm.ms1, MS, tid);
    __syncthreads();
    bias_silu_pass(sm.ms1, sm.cb1s, tid);  // ms1 = cf = silu(. + cb1)
    __syncthreads();

    // ---- edge_feat = cf @ c_w2  (32 edges x 8), packed-K FFMA2 ----
    {
        int e = tid >> 3;
        int j = tid & 7;
        ull acc = 0ull;
#pragma unroll 8
        for (int kp = 0; kp < 64; kp++) {
            ull cf = *(const ull*)&sm.ms1[e * MS + kp * 2];
            FMA2(acc, cf, g_CW2p[kp * 8 + j], acc);
        }
        sm.ef[e * 8 + j] = lo_f(acc) + hi_f(acc);
    }
    __syncthreads();

    // ---- aggregation atomics ----
    for (int idx = tid; idx < TILE_E * 128; idx += NTHR) {
        int e = idx >> 7, j = idx & 127;
        int t = sm.s_tgt[e];
        atomicAdd(&g_node_agg[(long)t * 128 + j], sm.ms2[e * MS + j] * sm.s_ew[e]);
    }
    if (tid < TILE_E * 8) {
        int e = tid >> 3, a = tid & 7;
        int t = sm.s_tgt[e];
        int ts = sm.s_ts[e];
        int w = 8 - ts;
        int hi = a + w; if (hi > 8) hi = 8;
        float s = 0.f;
        for (int b = a; b < hi; b++) s += sm.ef[e * 8 + b];
        float pe = (s / (float)w) * sm.s_wr[e];
        long ge = tileBase + e;
#pragma unroll
        for (int k = 0; k < 3; k++)
            atomicAdd(&g_coord_sum[(long)t * 24 + a * 3 + k],
                      g_cdiff[ge * 24 + a * 3 + k] * pe);
    }
    if (tid < TILE_E) {
        atomicAdd(&g_cnt[sm.s_tgt[tid]], 1.f);
    }
}

// ---------------- node epilogue: wmma het GEMM + BN + silu + residuals ----------------
__global__ __launch_bounds__(NTHR, 3)
void node_out_kernel(const float* __restrict__ h,
                     const float* __restrict__ coords,
                     const float* __restrict__ het_w,
                     const float* __restrict__ het_b,
                     const float* __restrict__ gamma,
                     const float* __restrict__ beta,
                     float* __restrict__ out) {
    __shared__ __align__(128) float ag[32 * MS];
    __shared__ __align__(128) float og[32 * MS];
    const int tid = threadIdx.x;
    const int base = blockIdx.x * 32;
    const float INVS = 0.9999950000374996f;  // 1/sqrt(1+1e-5)

    for (int idx = tid; idx < 32 * 128; idx += NTHR) {
        int n = idx >> 7, k = idx & 127;
        int gn = base + n;
        ag[n * MS + k] = (gn < NN) ? g_node_agg[(long)gn * 128 + k] : 0.f;
    }
    __syncthreads();

    // og = ag @ het_w (tf32 wmma)
    wmma_gemm_32x128x128(ag, het_w, og, MS, tid);
    __syncthreads();

    // epilogue: BN + silu + residual
    for (int idx = tid; idx < 32 * 32; idx += NTHR) {
        int n = idx >> 5, jq = idx & 31;
        int j = jq * 4;
        int gn = base + n;
        if (gn < NN) {
            float4 v  = *(const float4*)&og[n * MS + j];
            float4 hb = *(const float4*)&het_b[j];
            float4 gm = *(const float4*)&gamma[j];
            float4 bt = *(const float4*)&beta[j];
            float4 hv = *(const float4*)&h[(long)gn * 128 + j];
            float4 o;
            o.x = silu_f((v.x + hb.x) * INVS * gm.x + bt.x) + hv.x;
            o.y = silu_f((v.y + hb.y) * INVS * gm.y + bt.y) + hv.y;
            o.z = silu_f((v.z + hb.z) * INVS * gm.z + bt.z) + hv.z;
            o.w = silu_f((v.w + hb.w) * INVS * gm.w + bt.w) + hv.w;
            *(float4*)&out[(long)gn * 128 + j] = o;
        }
    }

    for (int idx = tid; idx < 32 * 24; idx += NTHR) {
        int n = idx / 24, k = idx % 24;
        int gn = base + n;
        if (gn < NN) {
            float c = fmaxf(g_cnt[gn], 1.f);
            out[(long)NN * 128 + (long)gn * 24 + k] =
                coords[(long)gn * 24 + k] + g_coord_sum[(long)gn * 24 + k] / c;
        }
    }
}

// ---------------- launch ----------------
extern "C" void kernel_launch(void* const* d_in, const int* in_sizes, int n_in,
                              void* d_out, int out_size) {
    (void)in_sizes; (void)n_in; (void)out_size;
    const float* h      = (const float*)d_in[0];
    const float* coords = (const float*)d_in[1];
    const float* ca     = (const float*)d_in[2];
    const float* cw     = (const float*)d_in[3];
    const float* ew     = (const float*)d_in[4];
    const int*   el     = (const int*)d_in[5];
    const float* rl_w   = (const float*)d_in[6];
    const float* rl_b   = (const float*)d_in[7];
    const float* m_w1   = (const float*)d_in[8];
    const float* m_b1   = (const float*)d_in[9];
    const float* m_w2   = (const float*)d_in[10];
    const float* m_b2   = (const float*)d_in[11];
    const float* c_w1   = (const float*)d_in[12];
    const float* c_b1   = (const float*)d_in[13];
    const float* c_w2   = (const float*)d_in[14];
    const float* het_w  = (const float*)d_in[15];
    const float* het_b  = (const float*)d_in[16];
    const float* gamma  = (const float*)d_in[17];
    const float* beta   = (const float*)d_in[18];
    const float* w_r    = (const float*)d_in[19];
    float* out = (float*)d_out;

    cudaFuncSetAttribute(edge_kernel, cudaFuncAttributeMaxDynamicSharedMemorySize,
                         (int)sizeof(EdgeSmem));

    zero_kernel<<<2048, 256>>>();
    pack_kernel<<<8, 64>>>(c_w2);
    node_pre_kernel<<<(NN + 255) / 256, 256>>>(coords, cw);
    node_gemm_kernel<<<(NN + 31) / 32, NTHR>>>(h, m_w1);
    max_kernel<<<(EE + 255) / 256, 256>>>(coords, el);
    edge_pre_kernel<<<(EE + 7) / 8, 256>>>(coords, ca, cw, ew, el, rl_w, rl_b, w_r);
    edge_kernel<<<EE / TILE_E, NTHR, sizeof(EdgeSmem)>>>(
        m_w1, m_b1, m_w2, m_b2, c_w1, c_b1);
    node_out_kernel<<<(NN + 31) / 32, NTHR>>>(h, coords, het_w, het_b, gamma, beta, out);
}